// round 1
// baseline (speedup 1.0000x reference)
#include <cuda_runtime.h>

#define BB 4
#define SS 2048
#define DD 1024
#define HH 16
#define DKH 64
#define MM (BB * SS)   // 8192

#define BQ 128
#define BKV 64
#define ATTN_SMEM_BYTES ((64 * 128 + 64 * 128 + 64 * 64) * 4)  // Qt + (Kt|Pt) + Vs = 80 KB

// ---------------- scratch (device globals: allocation-free rule) ----------------
__device__ float g_Q[(size_t)BB * HH * SS * DKH];
__device__ float g_K[(size_t)BB * HH * SS * DKH];
__device__ float g_V[(size_t)BB * HH * SS * DKH];
__device__ float g_attn[(size_t)BB * SS * DD];

// =====================================================================
// GEMM: C[M,N] = A[M,1024] @ B[1024,N] + bias, M=8192, N=K=1024.
// 128x128 tile, BK=8, 256 threads, 8x8 register tile per thread.
// split_heads=1 writes [b,h,s,dk] layout for attention.
// =====================================================================
__global__ __launch_bounds__(256) void gemm_bias_kernel(
    const float* __restrict__ A, const float* __restrict__ B,
    const float* __restrict__ bias, float* __restrict__ C, int split_heads)
{
    __shared__ float As[8][128];   // transposed: As[k][m]
    __shared__ float Bs[8][128];

    const int tid = threadIdx.x;
    const int tx = tid & 15;
    const int ty = tid >> 4;
    const int bm = blockIdx.y * 128;
    const int bn = blockIdx.x * 128;

    const int aRow = tid >> 1;          // 0..127
    const int aCol = (tid & 1) << 2;    // 0 or 4
    const int bRow = tid >> 5;          // 0..7
    const int bCol = (tid & 31) << 2;   // 0..124

    const float* Ap = A + (size_t)(bm + aRow) * DD + aCol;
    const float* Bp = B + (size_t)bRow * DD + bn + bCol;

    float acc[8][8];
#pragma unroll
    for (int i = 0; i < 8; i++)
#pragma unroll
        for (int j = 0; j < 8; j++) acc[i][j] = 0.f;

    for (int k0 = 0; k0 < DD; k0 += 8) {
        float4 av = *(const float4*)(Ap + k0);
        float4 bv = *(const float4*)(Bp + (size_t)k0 * DD);
        As[aCol + 0][aRow] = av.x;
        As[aCol + 1][aRow] = av.y;
        As[aCol + 2][aRow] = av.z;
        As[aCol + 3][aRow] = av.w;
        *(float4*)&Bs[bRow][bCol] = bv;
        __syncthreads();
#pragma unroll
        for (int kk = 0; kk < 8; kk++) {
            float a[8], b[8];
            *(float4*)&a[0] = *(const float4*)&As[kk][ty * 8];
            *(float4*)&a[4] = *(const float4*)&As[kk][ty * 8 + 4];
            *(float4*)&b[0] = *(const float4*)&Bs[kk][tx * 8];
            *(float4*)&b[4] = *(const float4*)&Bs[kk][tx * 8 + 4];
#pragma unroll
            for (int i = 0; i < 8; i++)
#pragma unroll
                for (int j = 0; j < 8; j++)
                    acc[i][j] = fmaf(a[i], b[j], acc[i][j]);
        }
        __syncthreads();
    }

#pragma unroll
    for (int i = 0; i < 8; i++) {
        const int m = bm + ty * 8 + i;
        const int bb = m >> 11;     // m / 2048
        const int s = m & 2047;
#pragma unroll
        for (int j4 = 0; j4 < 8; j4 += 4) {
            const int n = bn + tx * 8 + j4;
            float4 v;
            v.x = acc[i][j4 + 0] + bias[n + 0];
            v.y = acc[i][j4 + 1] + bias[n + 1];
            v.z = acc[i][j4 + 2] + bias[n + 2];
            v.w = acc[i][j4 + 3] + bias[n + 3];
            if (split_heads) {
                const int h = n >> 6;
                const int dk = n & 63;
                *(float4*)&C[(((size_t)(bb * HH + h)) * SS + s) * DKH + dk] = v;
            } else {
                *(float4*)&C[(size_t)m * DD + n] = v;
            }
        }
    }
}

// =====================================================================
// Flash attention, causal. One block: (b,h) x 128-row q tile.
// Qt/Kt/Pt stored transposed (reduction-dim-major) with XOR swizzle
// col' = col ^ (row & 28): conflict-free float4 reads, <=2-way stores.
// P aliases K's smem buffer (K fully consumed before P written).
// m/l kept in registers (replicated across the 16 lanes of a row group).
// =====================================================================
__global__ __launch_bounds__(256, 2) void attn_kernel(
    const float* __restrict__ Q, const float* __restrict__ K,
    const float* __restrict__ V, float* __restrict__ Out)
{
    extern __shared__ float sm[];
    float* Qt = sm;               // [64][128]  Qt[d][r]
    float* KP = sm + 64 * 128;    // Kt[64][64] then Pt[64][128]
    float* Vs = KP + 64 * 128;    // [64][64]   Vs[c][dk], natural

    const int tid = threadIdx.x;
    const int tx = tid & 15;
    const int ty = tid >> 4;
    const int qt = (SS / BQ - 1) - (int)blockIdx.x;   // heavy tiles first
    const int bh = blockIdx.y;

    const float* Qg = Q + (size_t)bh * SS * DKH + (size_t)qt * BQ * DKH;
    const float* Kg = K + (size_t)bh * SS * DKH;
    const float* Vg = V + (size_t)bh * SS * DKH;

    // load Q tile (128 x 64) transposed + swizzled, pre-scaled by 1/sqrt(dk)
#pragma unroll
    for (int t = 0; t < 8; t++) {
        int idx = tid + t * 256;
        int r = idx >> 4;               // 0..127
        int d4 = (idx & 15) << 2;       // 0..60
        float4 v = *(const float4*)(Qg + (size_t)r * DKH + d4);
        Qt[(d4 + 0) * 128 + (r ^ ((d4 + 0) & 28))] = v.x * 0.125f;
        Qt[(d4 + 1) * 128 + (r ^ ((d4 + 1) & 28))] = v.y * 0.125f;
        Qt[(d4 + 2) * 128 + (r ^ ((d4 + 2) & 28))] = v.z * 0.125f;
        Qt[(d4 + 3) * 128 + (r ^ ((d4 + 3) & 28))] = v.w * 0.125f;
    }

    float O[8][4];
    float mrow[8], lrow[8];
#pragma unroll
    for (int i = 0; i < 8; i++) {
        mrow[i] = -1e30f; lrow[i] = 0.f;
#pragma unroll
        for (int j = 0; j < 4; j++) O[i][j] = 0.f;
    }

    const int nkt = 2 * qt + 2;   // kv tiles needed for causal coverage
    for (int kt = 0; kt < nkt; kt++) {
        // load K (transposed + swizzled) and V (natural)
#pragma unroll
        for (int t = 0; t < 4; t++) {
            int idx = tid + t * 256;
            int c = idx >> 4;              // 0..63
            int d4 = (idx & 15) << 2;
            float4 kv = *(const float4*)(Kg + (size_t)(kt * BKV + c) * DKH + d4);
            KP[(d4 + 0) * 64 + (c ^ ((d4 + 0) & 28))] = kv.x;
            KP[(d4 + 1) * 64 + (c ^ ((d4 + 1) & 28))] = kv.y;
            KP[(d4 + 2) * 64 + (c ^ ((d4 + 2) & 28))] = kv.z;
            KP[(d4 + 3) * 64 + (c ^ ((d4 + 3) & 28))] = kv.w;
            float4 vv = *(const float4*)(Vg + (size_t)(kt * BKV + c) * DKH + d4);
            *(float4*)&Vs[c * 64 + d4] = vv;
        }
        __syncthreads();

        // scores: sc[i][j] = sum_d Q[8ty+i][d] * K[4tx+j][d]
        float sc[8][4];
#pragma unroll
        for (int i = 0; i < 8; i++)
#pragma unroll
            for (int j = 0; j < 4; j++) sc[i][j] = 0.f;

#pragma unroll 8
        for (int d = 0; d < 64; d++) {
            const int kq = d & 28;
            float a[8], b[4];
            *(float4*)&a[0] = *(const float4*)&Qt[d * 128 + ((8 * ty) ^ kq)];
            *(float4*)&a[4] = *(const float4*)&Qt[d * 128 + ((8 * ty + 4) ^ kq)];
            *(float4*)&b[0] = *(const float4*)&KP[d * 64 + ((4 * tx) ^ kq)];
#pragma unroll
            for (int i = 0; i < 8; i++)
#pragma unroll
                for (int j = 0; j < 4; j++)
                    sc[i][j] = fmaf(a[i], b[j], sc[i][j]);
        }

        // causal mask only on diagonal-crossing tiles
        if (kt >= 2 * qt) {
            const int qbase = qt * BQ + 8 * ty;
            const int kbase = kt * BKV + 4 * tx;
#pragma unroll
            for (int i = 0; i < 8; i++)
#pragma unroll
                for (int j = 0; j < 4; j++)
                    if (kbase + j > qbase + i) sc[i][j] = -1e30f;
        }

        // online softmax (reduction across the 16 lanes sharing a row group)
#pragma unroll
        for (int i = 0; i < 8; i++) {
            float t = fmaxf(fmaxf(sc[i][0], sc[i][1]), fmaxf(sc[i][2], sc[i][3]));
            t = fmaxf(t, __shfl_xor_sync(0xffffffffu, t, 8));
            t = fmaxf(t, __shfl_xor_sync(0xffffffffu, t, 4));
            t = fmaxf(t, __shfl_xor_sync(0xffffffffu, t, 2));
            t = fmaxf(t, __shfl_xor_sync(0xffffffffu, t, 1));
            const float mnew = fmaxf(mrow[i], t);
            const float escf = __expf(mrow[i] - mnew);
            float rs = 0.f;
#pragma unroll
            for (int j = 0; j < 4; j++) {
                sc[i][j] = __expf(sc[i][j] - mnew);
                rs += sc[i][j];
            }
            rs += __shfl_xor_sync(0xffffffffu, rs, 8);
            rs += __shfl_xor_sync(0xffffffffu, rs, 4);
            rs += __shfl_xor_sync(0xffffffffu, rs, 2);
            rs += __shfl_xor_sync(0xffffffffu, rs, 1);
            lrow[i] = lrow[i] * escf + rs;
            mrow[i] = mnew;
#pragma unroll
            for (int j = 0; j < 4; j++) O[i][j] *= escf;
        }

        __syncthreads();   // Kt fully consumed -> safe to overwrite with Pt

        // store P transposed + swizzled: Pt[c][r ^ (c & 28)]
#pragma unroll
        for (int j = 0; j < 4; j++) {
            const int c = 4 * tx + j;
            const int cs = c & 28;
            float* prow = &KP[c * 128];
#pragma unroll
            for (int i = 0; i < 8; i++)
                prow[(8 * ty + i) ^ cs] = sc[i][j];
        }
        __syncthreads();

        // O += P @ V
#pragma unroll 8
        for (int c = 0; c < 64; c++) {
            const int kc = c & 28;
            float a[8], b[4];
            *(float4*)&a[0] = *(const float4*)&KP[c * 128 + ((8 * ty) ^ kc)];
            *(float4*)&a[4] = *(const float4*)&KP[c * 128 + ((8 * ty + 4) ^ kc)];
            *(float4*)&b[0] = *(const float4*)&Vs[c * 64 + 4 * tx];
#pragma unroll
            for (int i = 0; i < 8; i++)
#pragma unroll
                for (int j = 0; j < 4; j++)
                    O[i][j] = fmaf(a[i], b[j], O[i][j]);
        }
        __syncthreads();   // protect KP/Vs before next tile's loads
    }

    // write combined-head layout [b, s, h*64 + dk]
    const int b = bh >> 4;
    const int h = bh & 15;
#pragma unroll
    for (int i = 0; i < 8; i++) {
        const int q = qt * BQ + 8 * ty + i;
        const float inv = 1.f / lrow[i];
        float4 v;
        v.x = O[i][0] * inv; v.y = O[i][1] * inv;
        v.z = O[i][2] * inv; v.w = O[i][3] * inv;
        *(float4*)&Out[((size_t)(b * SS + q)) * DD + h * DKH + 4 * tx] = v;
    }
}

// =====================================================================
extern "C" void kernel_launch(void* const* d_in, const int* in_sizes, int n_in,
                              void* d_out, int out_size)
{
    (void)in_sizes; (void)n_in; (void)out_size;
    const float* x  = (const float*)d_in[0];
    // d_in[1] = attn_mask (deterministic causal tril) -- structure hard-coded
    const float* Wq = (const float*)d_in[2];
    const float* bq = (const float*)d_in[3];
    const float* Wk = (const float*)d_in[4];
    const float* bk = (const float*)d_in[5];
    const float* Wv = (const float*)d_in[6];
    const float* bv = (const float*)d_in[7];
    const float* Wo = (const float*)d_in[8];
    const float* bo = (const float*)d_in[9];
    float* out = (float*)d_out;

    float *qp, *kp, *vp, *ap;
    cudaGetSymbolAddress((void**)&qp, g_Q);
    cudaGetSymbolAddress((void**)&kp, g_K);
    cudaGetSymbolAddress((void**)&vp, g_V);
    cudaGetSymbolAddress((void**)&ap, g_attn);

    cudaFuncSetAttribute(attn_kernel,
                         cudaFuncAttributeMaxDynamicSharedMemorySize,
                         ATTN_SMEM_BYTES);

    const dim3 gg(DD / 128, MM / 128);   // (8, 64)
    gemm_bias_kernel<<<gg, 256>>>(x, Wq, bq, qp, 1);
    gemm_bias_kernel<<<gg, 256>>>(x, Wk, bk, kp, 1);
    gemm_bias_kernel<<<gg, 256>>>(x, Wv, bv, vp, 1);
    attn_kernel<<<dim3(SS / BQ, BB * HH), 256, ATTN_SMEM_BYTES>>>(qp, kp, vp, ap);
    gemm_bias_kernel<<<gg, 256>>>(ap, Wo, bo, out, 0);
}

// round 3
// speedup vs baseline: 1.4396x; 1.4396x over previous
#include <cuda_runtime.h>
#include <cuda_bf16.h>
#include <cstdint>

#define BB 4
#define SS 2048
#define DD 1024
#define HH 16
#define DKH 64
#define MM (BB * SS)   // 8192

#define BQ 128
#define BKV 64
#define ATTN_SMEM_BYTES ((64 * 128 + 64 * 128 + 64 * 64) * 4)  // 80 KB

// GEMM (HMMA) config: CTA 128x128, BK=32, double-buffered
#define GBM 128
#define GBN 128
#define GBK 32
#define STAGE_BYTES (4 * GBM * GBK * 2)      // Ah,Al,Bh,Bl tiles = 32 KB
#define GEMM_SMEM_BYTES (2 * STAGE_BYTES)    // 64 KB
#define NIT (DD / GBK)                       // 32

// ---------------- scratch (device globals: allocation-free rule) ----------------
__device__ float g_Q[(size_t)MM * DD];
__device__ float g_K[(size_t)MM * DD];
__device__ float g_V[(size_t)MM * DD];
__device__ float g_attn[(size_t)MM * DD];
__device__ __nv_bfloat16 g_xh[(size_t)MM * DD];
__device__ __nv_bfloat16 g_xl[(size_t)MM * DD];
__device__ __nv_bfloat16 g_ah[(size_t)MM * DD];
__device__ __nv_bfloat16 g_al[(size_t)MM * DD];
__device__ __nv_bfloat16 g_Wth[4][(size_t)DD * DD];  // W^T hi, [n][k]
__device__ __nv_bfloat16 g_Wtl[4][(size_t)DD * DD];  // W^T lo

// ---------------- PTX helpers ----------------
__device__ __forceinline__ uint32_t smem_u32(const void* p) {
    uint32_t a;
    asm("{ .reg .u64 t; cvta.to.shared.u64 t, %1; cvt.u32.u64 %0, t; }"
        : "=r"(a) : "l"(p));
    return a;
}

#define LDSM_X4(r, addr) \
    asm volatile("ldmatrix.sync.aligned.m8n8.x4.shared.b16 {%0,%1,%2,%3}, [%4];" \
                 : "=r"((r)[0]), "=r"((r)[1]), "=r"((r)[2]), "=r"((r)[3]) : "r"(addr))

#define MMA_BF16(d, a, b) \
    asm volatile("mma.sync.aligned.m16n8k16.row.col.f32.bf16.bf16.f32 " \
                 "{%0,%1,%2,%3}, {%4,%5,%6,%7}, {%8,%9}, {%0,%1,%2,%3};" \
                 : "+f"((d)[0]), "+f"((d)[1]), "+f"((d)[2]), "+f"((d)[3]) \
                 : "r"((a)[0]), "r"((a)[1]), "r"((a)[2]), "r"((a)[3]), \
                   "r"((b)[0]), "r"((b)[1]))

#define CP16(saddr, gptr) \
    asm volatile("cp.async.cg.shared.global [%0], [%1], 16;" \
                 :: "r"(saddr), "l"(gptr))
#define CP_COMMIT() asm volatile("cp.async.commit_group;" ::: "memory")
#define CP_WAIT(n)  asm volatile("cp.async.wait_group %0;" :: "n"(n) : "memory")

// swizzled byte offset within a [rows][32 bf16] tile (row pitch 64B, 4 chunks)
__device__ __forceinline__ uint32_t swz(int r, int c) {
    return (uint32_t)(r * 64 + ((c ^ ((r >> 1) & 3)) << 4));
}

// =====================================================================
// split fp32 -> bf16 hi + bf16 lo (residual)
// =====================================================================
__global__ void split_bf16_kernel(const float* __restrict__ in,
                                  __nv_bfloat16* __restrict__ hi,
                                  __nv_bfloat16* __restrict__ lo, int n4)
{
    int i = blockIdx.x * blockDim.x + threadIdx.x;
    if (i >= n4) return;
    float4 v = ((const float4*)in)[i];
    __nv_bfloat16 h0 = __float2bfloat16(v.x);
    __nv_bfloat16 h1 = __float2bfloat16(v.y);
    __nv_bfloat16 h2 = __float2bfloat16(v.z);
    __nv_bfloat16 h3 = __float2bfloat16(v.w);
    __nv_bfloat162 hv0; hv0.x = h0; hv0.y = h1;
    __nv_bfloat162 hv1; hv1.x = h2; hv1.y = h3;
    __nv_bfloat162 lv0, lv1;
    lv0.x = __float2bfloat16(v.x - __bfloat162float(h0));
    lv0.y = __float2bfloat16(v.y - __bfloat162float(h1));
    lv1.x = __float2bfloat16(v.z - __bfloat162float(h2));
    lv1.y = __float2bfloat16(v.w - __bfloat162float(h3));
    ((__nv_bfloat162*)hi)[2 * i]     = hv0;
    ((__nv_bfloat162*)hi)[2 * i + 1] = hv1;
    ((__nv_bfloat162*)lo)[2 * i]     = lv0;
    ((__nv_bfloat162*)lo)[2 * i + 1] = lv1;
}

// =====================================================================
// W[k][n] fp32 -> Wt_hi[n][k], Wt_lo[n][k] bf16 (transpose + split)
// =====================================================================
__global__ void transpose_split_kernel(const float* __restrict__ W,
                                       __nv_bfloat16* __restrict__ Th,
                                       __nv_bfloat16* __restrict__ Tl)
{
    __shared__ float s[32][33];
    const int tx = threadIdx.x, ty = threadIdx.y;
    const int x0 = blockIdx.x * 32, y0 = blockIdx.y * 32;
#pragma unroll
    for (int j = 0; j < 32; j += 8)
        s[ty + j][tx] = W[(size_t)(y0 + ty + j) * DD + x0 + tx];
    __syncthreads();
#pragma unroll
    for (int j = 0; j < 32; j += 8) {
        float v = s[tx][ty + j];
        __nv_bfloat16 h = __float2bfloat16(v);
        __nv_bfloat16 l = __float2bfloat16(v - __bfloat162float(h));
        size_t o = (size_t)(x0 + ty + j) * DD + y0 + tx;
        Th[o] = h; Tl[o] = l;
    }
}

// =====================================================================
// Tensor-core GEMM via mma.sync (HMMA): C = (Ah+Al) @ (Bh+Bl)^T + bias
// 3-term split-bf16. CTA 128x128, BK=32, cp.async double buffer.
// =====================================================================
__global__ __launch_bounds__(256) void gemm_mma_kernel(
    const __nv_bfloat16* __restrict__ Ah, const __nv_bfloat16* __restrict__ Al,
    const __nv_bfloat16* __restrict__ Bh, const __nv_bfloat16* __restrict__ Bl,
    const float* __restrict__ bias, float* __restrict__ C, int split_heads)
{
    extern __shared__ char smc[];
    const uint32_t sb = smem_u32(smc);

    const int tid = threadIdx.x;
    const int wid = tid >> 5;
    const int lane = tid & 31;
    const int bm = blockIdx.y * GBM;
    const int bn = blockIdx.x * GBN;

    // ---- cp.async load mapping: thread -> (row, 2 chunks of 16B) ----
    const int lr = tid >> 1;             // 0..127
    const int lc = (tid & 1) * 2;        // chunk 0 or 2
    const __nv_bfloat16* gAh = Ah + (size_t)(bm + lr) * DD + lc * 8;
    const __nv_bfloat16* gAl = Al + (size_t)(bm + lr) * DD + lc * 8;
    const __nv_bfloat16* gBh = Bh + (size_t)(bn + lr) * DD + lc * 8;
    const __nv_bfloat16* gBl = Bl + (size_t)(bn + lr) * DD + lc * 8;
    const uint32_t so0 = swz(lr, lc);
    const uint32_t so1 = swz(lr, lc + 1);

    // ---- warp tiling: 4(M) x 2(N); warp tile 32x64 ----
    const int wm = (wid & 3) * 32;
    const int wn = (wid >> 2) * 64;

    float acc[2][8][4];
#pragma unroll
    for (int i = 0; i < 2; i++)
#pragma unroll
        for (int j = 0; j < 8; j++)
#pragma unroll
            for (int q = 0; q < 4; q++) acc[i][j][q] = 0.f;

    // issue stage 0
    {
        const uint32_t st = sb;
        CP16(st + so0,          gAh);      CP16(st + so1,          gAh + 8);
        CP16(st + 8192  + so0,  gAl);      CP16(st + 8192  + so1,  gAl + 8);
        CP16(st + 16384 + so0,  gBh);      CP16(st + 16384 + so1,  gBh + 8);
        CP16(st + 24576 + so0,  gBl);      CP16(st + 24576 + so1,  gBl + 8);
        CP_COMMIT();
    }

    for (int it = 0; it < NIT; ++it) {
        if (it + 1 < NIT) {
            const uint32_t st = sb + ((it + 1) & 1) * STAGE_BYTES;
            const int koff = (it + 1) * GBK;
            CP16(st + so0,          gAh + koff);  CP16(st + so1,          gAh + koff + 8);
            CP16(st + 8192  + so0,  gAl + koff);  CP16(st + 8192  + so1,  gAl + koff + 8);
            CP16(st + 16384 + so0,  gBh + koff);  CP16(st + 16384 + so1,  gBh + koff + 8);
            CP16(st + 24576 + so0,  gBl + koff);  CP16(st + 24576 + so1,  gBl + koff + 8);
            CP_COMMIT();
            CP_WAIT(1);
        } else {
            CP_WAIT(0);
        }
        __syncthreads();

        const uint32_t st = sb + (it & 1) * STAGE_BYTES;
        const uint32_t sAh = st;
        const uint32_t sAl = st + 8192;
        const uint32_t sBh = st + 16384;
        const uint32_t sBl = st + 24576;

#pragma unroll
        for (int s = 0; s < 2; s++) {
            const int c = s * 2 + (lane >> 4);        // chunk for this lane
            // A fragments (2 m-tiles, hi+lo)
            uint32_t ah[2][4], al[2][4];
#pragma unroll
            for (int i = 0; i < 2; i++) {
                const int r = wm + i * 16 + (lane & 15);
                const uint32_t off = swz(r, c);
                LDSM_X4(ah[i], sAh + off);
                LDSM_X4(al[i], sAl + off);
            }
            // B fragments (8 n-tiles via 4 x4-ldmatrix, hi+lo)
            uint32_t bh[8][2], bl[8][2];
#pragma unroll
            for (int j2 = 0; j2 < 4; j2++) {
                const int n = wn + j2 * 16 + (lane & 15);
                const uint32_t off = swz(n, c);
                uint32_t t[4];
                LDSM_X4(t, sBh + off);
                bh[2 * j2][0] = t[0]; bh[2 * j2][1] = t[2];
                bh[2 * j2 + 1][0] = t[1]; bh[2 * j2 + 1][1] = t[3];
                LDSM_X4(t, sBl + off);
                bl[2 * j2][0] = t[0]; bl[2 * j2][1] = t[2];
                bl[2 * j2 + 1][0] = t[1]; bl[2 * j2 + 1][1] = t[3];
            }
#pragma unroll
            for (int i = 0; i < 2; i++)
#pragma unroll
                for (int j = 0; j < 8; j++) {
                    MMA_BF16(acc[i][j], ah[i], bh[j]);
                    MMA_BF16(acc[i][j], ah[i], bl[j]);
                    MMA_BF16(acc[i][j], al[i], bh[j]);
                }
        }
        __syncthreads();
    }

    // ---- epilogue: bias + store (optionally split-head layout) ----
    const int lrow = lane >> 2;          // 0..7
    const int lcol = (lane & 3) * 2;     // 0,2,4,6
#pragma unroll
    for (int i = 0; i < 2; i++) {
#pragma unroll
        for (int j = 0; j < 8; j++) {
            const int col = bn + wn + j * 8 + lcol;
            const float b0 = __ldg(&bias[col]);
            const float b1 = __ldg(&bias[col + 1]);
#pragma unroll
            for (int half = 0; half < 2; half++) {
                const int m = bm + wm + i * 16 + lrow + half * 8;
                float2 v;
                v.x = acc[i][j][2 * half + 0] + b0;
                v.y = acc[i][j][2 * half + 1] + b1;
                if (split_heads) {
                    const int bb = m >> 11;
                    const int s = m & 2047;
                    const int h = col >> 6;
                    const int dk = col & 63;
                    *(float2*)&C[(((size_t)(bb * HH + h)) * SS + s) * DKH + dk] = v;
                } else {
                    *(float2*)&C[(size_t)m * DD + col] = v;
                }
            }
        }
    }
}

// =====================================================================
// Flash attention, causal (SIMT fp32 — unchanged from round 1).
// =====================================================================
__global__ __launch_bounds__(256, 2) void attn_kernel(
    const float* __restrict__ Q, const float* __restrict__ K,
    const float* __restrict__ V, float* __restrict__ Out)
{
    extern __shared__ float smf[];
    float* Qt = smf;
    float* KP = smf + 64 * 128;
    float* Vs = KP + 64 * 128;

    const int tid = threadIdx.x;
    const int tx = tid & 15;
    const int ty = tid >> 4;
    const int qt = (SS / BQ - 1) - (int)blockIdx.x;
    const int bh = blockIdx.y;

    const float* Qg = Q + (size_t)bh * SS * DKH + (size_t)qt * BQ * DKH;
    const float* Kg = K + (size_t)bh * SS * DKH;
    const float* Vg = V + (size_t)bh * SS * DKH;

#pragma unroll
    for (int t = 0; t < 8; t++) {
        int idx = tid + t * 256;
        int r = idx >> 4;
        int d4 = (idx & 15) << 2;
        float4 v = *(const float4*)(Qg + (size_t)r * DKH + d4);
        Qt[(d4 + 0) * 128 + (r ^ ((d4 + 0) & 28))] = v.x * 0.125f;
        Qt[(d4 + 1) * 128 + (r ^ ((d4 + 1) & 28))] = v.y * 0.125f;
        Qt[(d4 + 2) * 128 + (r ^ ((d4 + 2) & 28))] = v.z * 0.125f;
        Qt[(d4 + 3) * 128 + (r ^ ((d4 + 3) & 28))] = v.w * 0.125f;
    }

    float O[8][4];
    float mrow[8], lrow[8];
#pragma unroll
    for (int i = 0; i < 8; i++) {
        mrow[i] = -1e30f; lrow[i] = 0.f;
#pragma unroll
        for (int j = 0; j < 4; j++) O[i][j] = 0.f;
    }

    const int nkt = 2 * qt + 2;
    for (int kt = 0; kt < nkt; kt++) {
#pragma unroll
        for (int t = 0; t < 4; t++) {
            int idx = tid + t * 256;
            int c = idx >> 4;
            int d4 = (idx & 15) << 2;
            float4 kv = *(const float4*)(Kg + (size_t)(kt * BKV + c) * DKH + d4);
            KP[(d4 + 0) * 64 + (c ^ ((d4 + 0) & 28))] = kv.x;
            KP[(d4 + 1) * 64 + (c ^ ((d4 + 1) & 28))] = kv.y;
            KP[(d4 + 2) * 64 + (c ^ ((d4 + 2) & 28))] = kv.z;
            KP[(d4 + 3) * 64 + (c ^ ((d4 + 3) & 28))] = kv.w;
            float4 vv = *(const float4*)(Vg + (size_t)(kt * BKV + c) * DKH + d4);
            *(float4*)&Vs[c * 64 + d4] = vv;
        }
        __syncthreads();

        float sc[8][4];
#pragma unroll
        for (int i = 0; i < 8; i++)
#pragma unroll
            for (int j = 0; j < 4; j++) sc[i][j] = 0.f;

#pragma unroll 8
        for (int d = 0; d < 64; d++) {
            const int kq = d & 28;
            float a[8], b[4];
            *(float4*)&a[0] = *(const float4*)&Qt[d * 128 + ((8 * ty) ^ kq)];
            *(float4*)&a[4] = *(const float4*)&Qt[d * 128 + ((8 * ty + 4) ^ kq)];
            *(float4*)&b[0] = *(const float4*)&KP[d * 64 + ((4 * tx) ^ kq)];
#pragma unroll
            for (int i = 0; i < 8; i++)
#pragma unroll
                for (int j = 0; j < 4; j++)
                    sc[i][j] = fmaf(a[i], b[j], sc[i][j]);
        }

        if (kt >= 2 * qt) {
            const int qbase = qt * BQ + 8 * ty;
            const int kbase = kt * BKV + 4 * tx;
#pragma unroll
            for (int i = 0; i < 8; i++)
#pragma unroll
                for (int j = 0; j < 4; j++)
                    if (kbase + j > qbase + i) sc[i][j] = -1e30f;
        }

#pragma unroll
        for (int i = 0; i < 8; i++) {
            float t = fmaxf(fmaxf(sc[i][0], sc[i][1]), fmaxf(sc[i][2], sc[i][3]));
            t = fmaxf(t, __shfl_xor_sync(0xffffffffu, t, 8));
            t = fmaxf(t, __shfl_xor_sync(0xffffffffu, t, 4));
            t = fmaxf(t, __shfl_xor_sync(0xffffffffu, t, 2));
            t = fmaxf(t, __shfl_xor_sync(0xffffffffu, t, 1));
            const float mnew = fmaxf(mrow[i], t);
            const float escf = __expf(mrow[i] - mnew);
            float rs = 0.f;
#pragma unroll
            for (int j = 0; j < 4; j++) {
                sc[i][j] = __expf(sc[i][j] - mnew);
                rs += sc[i][j];
            }
            rs += __shfl_xor_sync(0xffffffffu, rs, 8);
            rs += __shfl_xor_sync(0xffffffffu, rs, 4);
            rs += __shfl_xor_sync(0xffffffffu, rs, 2);
            rs += __shfl_xor_sync(0xffffffffu, rs, 1);
            lrow[i] = lrow[i] * escf + rs;
            mrow[i] = mnew;
#pragma unroll
            for (int j = 0; j < 4; j++) O[i][j] *= escf;
        }

        __syncthreads();

#pragma unroll
        for (int j = 0; j < 4; j++) {
            const int c = 4 * tx + j;
            const int cs = c & 28;
            float* prow = &KP[c * 128];
#pragma unroll
            for (int i = 0; i < 8; i++)
                prow[(8 * ty + i) ^ cs] = sc[i][j];
        }
        __syncthreads();

#pragma unroll 8
        for (int c = 0; c < 64; c++) {
            const int kc = c & 28;
            float a[8], b[4];
            *(float4*)&a[0] = *(const float4*)&KP[c * 128 + ((8 * ty) ^ kc)];
            *(float4*)&a[4] = *(const float4*)&KP[c * 128 + ((8 * ty + 4) ^ kc)];
            *(float4*)&b[0] = *(const float4*)&Vs[c * 64 + 4 * tx];
#pragma unroll
            for (int i = 0; i < 8; i++)
#pragma unroll
                for (int j = 0; j < 4; j++)
                    O[i][j] = fmaf(a[i], b[j], O[i][j]);
        }
        __syncthreads();
    }

    const int b = bh >> 4;
    const int h = bh & 15;
#pragma unroll
    for (int i = 0; i < 8; i++) {
        const int q = qt * BQ + 8 * ty + i;
        const float inv = 1.f / lrow[i];
        float4 v;
        v.x = O[i][0] * inv; v.y = O[i][1] * inv;
        v.z = O[i][2] * inv; v.w = O[i][3] * inv;
        *(float4*)&Out[((size_t)(b * SS + q)) * DD + h * DKH + 4 * tx] = v;
    }
}

// =====================================================================
extern "C" void kernel_launch(void* const* d_in, const int* in_sizes, int n_in,
                              void* d_out, int out_size)
{
    (void)in_sizes; (void)n_in; (void)out_size;
    const float* x  = (const float*)d_in[0];
    const float* Wq = (const float*)d_in[2];
    const float* bq = (const float*)d_in[3];
    const float* Wk = (const float*)d_in[4];
    const float* bk = (const float*)d_in[5];
    const float* Wv = (const float*)d_in[6];
    const float* bv = (const float*)d_in[7];
    const float* Wo = (const float*)d_in[8];
    const float* bo = (const float*)d_in[9];
    float* out = (float*)d_out;

    float *qp, *kp, *vp, *ap;
    __nv_bfloat16 *xh, *xl, *ah, *al, *wth, *wtl;
    cudaGetSymbolAddress((void**)&qp, g_Q);
    cudaGetSymbolAddress((void**)&kp, g_K);
    cudaGetSymbolAddress((void**)&vp, g_V);
    cudaGetSymbolAddress((void**)&ap, g_attn);
    cudaGetSymbolAddress((void**)&xh, g_xh);
    cudaGetSymbolAddress((void**)&xl, g_xl);
    cudaGetSymbolAddress((void**)&ah, g_ah);
    cudaGetSymbolAddress((void**)&al, g_al);
    cudaGetSymbolAddress((void**)&wth, g_Wth);
    cudaGetSymbolAddress((void**)&wtl, g_Wtl);

    cudaFuncSetAttribute(attn_kernel,
                         cudaFuncAttributeMaxDynamicSharedMemorySize,
                         ATTN_SMEM_BYTES);
    cudaFuncSetAttribute(gemm_mma_kernel,
                         cudaFuncAttributeMaxDynamicSharedMemorySize,
                         GEMM_SMEM_BYTES);

    const int n4 = MM * DD / 4;
    const dim3 tg(32, 32);
    const dim3 tb(32, 8);
    const dim3 gg(DD / GBN, MM / GBM);   // (8, 64)

    // prepass: split x, transpose+split weights
    split_bf16_kernel<<<(n4 + 255) / 256, 256>>>(x, xh, xl, n4);
    transpose_split_kernel<<<tg, tb>>>(Wq, wth + 0 * (size_t)DD * DD, wtl + 0 * (size_t)DD * DD);
    transpose_split_kernel<<<tg, tb>>>(Wk, wth + 1 * (size_t)DD * DD, wtl + 1 * (size_t)DD * DD);
    transpose_split_kernel<<<tg, tb>>>(Wv, wth + 2 * (size_t)DD * DD, wtl + 2 * (size_t)DD * DD);
    transpose_split_kernel<<<tg, tb>>>(Wo, wth + 3 * (size_t)DD * DD, wtl + 3 * (size_t)DD * DD);

    // QKV projections (tensor cores via mma.sync)
    gemm_mma_kernel<<<gg, 256, GEMM_SMEM_BYTES>>>(xh, xl, wth + 0 * (size_t)DD * DD, wtl + 0 * (size_t)DD * DD, bq, qp, 1);
    gemm_mma_kernel<<<gg, 256, GEMM_SMEM_BYTES>>>(xh, xl, wth + 1 * (size_t)DD * DD, wtl + 1 * (size_t)DD * DD, bk, kp, 1);
    gemm_mma_kernel<<<gg, 256, GEMM_SMEM_BYTES>>>(xh, xl, wth + 2 * (size_t)DD * DD, wtl + 2 * (size_t)DD * DD, bv, vp, 1);

    // attention
    attn_kernel<<<dim3(SS / BQ, BB * HH), 256, ATTN_SMEM_BYTES>>>(qp, kp, vp, ap);

    // output projection
    split_bf16_kernel<<<(n4 + 255) / 256, 256>>>(ap, ah, al, n4);
    gemm_mma_kernel<<<gg, 256, GEMM_SMEM_BYTES>>>(ah, al, wth + 3 * (size_t)DD * DD, wtl + 3 * (size_t)DD * DD, bo, out, 0);
}

// round 4
// speedup vs baseline: 1.4517x; 1.0084x over previous
#include <cuda_runtime.h>
#include <cuda_bf16.h>
#include <cstdint>

#define BB 4
#define SS 2048
#define DD 1024
#define HH 16
#define DKH 64
#define MM (BB * SS)   // 8192

#define BQ 128
#define BKV 64
#define ATTN_SMEM_BYTES ((64 * 128 + 64 * 128 + 64 * 64) * 4)  // 80 KB

// GEMM (HMMA) config: CTA 128x128, BK=32, double-buffered
#define GBM 128
#define GBN 128
#define GBK 32
#define STAGE_BYTES (4 * GBM * GBK * 2)      // Ah,Al,Bh,Bl tiles = 32 KB
#define GEMM_SMEM_BYTES (2 * STAGE_BYTES)    // 64 KB
#define NIT (DD / GBK)                       // 32

// ---------------- scratch (device globals: allocation-free rule) ----------------
__device__ float g_Q[(size_t)MM * DD];
__device__ float g_K[(size_t)MM * DD];
__device__ float g_V[(size_t)MM * DD];
__device__ float g_attn[(size_t)MM * DD];
__device__ __nv_bfloat16 g_xh[(size_t)MM * DD];
__device__ __nv_bfloat16 g_xl[(size_t)MM * DD];
__device__ __nv_bfloat16 g_ah[(size_t)MM * DD];
__device__ __nv_bfloat16 g_al[(size_t)MM * DD];
__device__ __nv_bfloat16 g_Wth[4][(size_t)DD * DD];  // W^T hi, [n][k]
__device__ __nv_bfloat16 g_Wtl[4][(size_t)DD * DD];  // W^T lo

// ---------------- PTX helpers ----------------
__device__ __forceinline__ uint32_t smem_u32(const void* p) {
    uint32_t a;
    asm("{ .reg .u64 t; cvta.to.shared.u64 t, %1; cvt.u32.u64 %0, t; }"
        : "=r"(a) : "l"(p));
    return a;
}

#define LDSM_X4(r, addr) \
    asm volatile("ldmatrix.sync.aligned.m8n8.x4.shared.b16 {%0,%1,%2,%3}, [%4];" \
                 : "=r"((r)[0]), "=r"((r)[1]), "=r"((r)[2]), "=r"((r)[3]) : "r"(addr))

#define MMA_BF16(d, a, b) \
    asm volatile("mma.sync.aligned.m16n8k16.row.col.f32.bf16.bf16.f32 " \
                 "{%0,%1,%2,%3}, {%4,%5,%6,%7}, {%8,%9}, {%0,%1,%2,%3};" \
                 : "+f"((d)[0]), "+f"((d)[1]), "+f"((d)[2]), "+f"((d)[3]) \
                 : "r"((a)[0]), "r"((a)[1]), "r"((a)[2]), "r"((a)[3]), \
                   "r"((b)[0]), "r"((b)[1]))

#define CP16(saddr, gptr) \
    asm volatile("cp.async.cg.shared.global [%0], [%1], 16;" \
                 :: "r"(saddr), "l"(gptr))
#define CP_COMMIT() asm volatile("cp.async.commit_group;" ::: "memory")
#define CP_WAIT(n)  asm volatile("cp.async.wait_group %0;" :: "n"(n) : "memory")

// swizzled byte offset within a [rows][32 bf16] tile (row pitch 64B, 4 chunks)
__device__ __forceinline__ uint32_t swz(int r, int c) {
    return (uint32_t)(r * 64 + ((c ^ ((r >> 1) & 3)) << 4));
}

// =====================================================================
// split fp32 -> bf16 hi + bf16 lo (residual)
// =====================================================================
__global__ void split_bf16_kernel(const float* __restrict__ in,
                                  __nv_bfloat16* __restrict__ hi,
                                  __nv_bfloat16* __restrict__ lo, int n4)
{
    int i = blockIdx.x * blockDim.x + threadIdx.x;
    if (i >= n4) return;
    float4 v = ((const float4*)in)[i];
    __nv_bfloat16 h0 = __float2bfloat16(v.x);
    __nv_bfloat16 h1 = __float2bfloat16(v.y);
    __nv_bfloat16 h2 = __float2bfloat16(v.z);
    __nv_bfloat16 h3 = __float2bfloat16(v.w);
    __nv_bfloat162 hv0; hv0.x = h0; hv0.y = h1;
    __nv_bfloat162 hv1; hv1.x = h2; hv1.y = h3;
    __nv_bfloat162 lv0, lv1;
    lv0.x = __float2bfloat16(v.x - __bfloat162float(h0));
    lv0.y = __float2bfloat16(v.y - __bfloat162float(h1));
    lv1.x = __float2bfloat16(v.z - __bfloat162float(h2));
    lv1.y = __float2bfloat16(v.w - __bfloat162float(h3));
    ((__nv_bfloat162*)hi)[2 * i]     = hv0;
    ((__nv_bfloat162*)hi)[2 * i + 1] = hv1;
    ((__nv_bfloat162*)lo)[2 * i]     = lv0;
    ((__nv_bfloat162*)lo)[2 * i + 1] = lv1;
}

// =====================================================================
// W[k][n] fp32 -> Wt_hi[n][k], Wt_lo[n][k] bf16 (transpose + split)
// =====================================================================
__global__ void transpose_split_kernel(const float* __restrict__ W,
                                       __nv_bfloat16* __restrict__ Th,
                                       __nv_bfloat16* __restrict__ Tl)
{
    __shared__ float s[32][33];
    const int tx = threadIdx.x, ty = threadIdx.y;
    const int x0 = blockIdx.x * 32, y0 = blockIdx.y * 32;
#pragma unroll
    for (int j = 0; j < 32; j += 8)
        s[ty + j][tx] = W[(size_t)(y0 + ty + j) * DD + x0 + tx];
    __syncthreads();
#pragma unroll
    for (int j = 0; j < 32; j += 8) {
        float v = s[tx][ty + j];
        __nv_bfloat16 h = __float2bfloat16(v);
        __nv_bfloat16 l = __float2bfloat16(v - __bfloat162float(h));
        size_t o = (size_t)(x0 + ty + j) * DD + y0 + tx;
        Th[o] = h; Tl[o] = l;
    }
}

// =====================================================================
// Tensor-core GEMM via mma.sync (HMMA): C = (Ah+Al) @ (Bh+Bl)^T + bias
// 3-term split-bf16. CTA 128x128, BK=32, cp.async double buffer.
// =====================================================================
__global__ __launch_bounds__(256) void gemm_mma_kernel(
    const __nv_bfloat16* __restrict__ Ah, const __nv_bfloat16* __restrict__ Al,
    const __nv_bfloat16* __restrict__ Bh, const __nv_bfloat16* __restrict__ Bl,
    const float* __restrict__ bias, float* __restrict__ C, int split_heads)
{
    extern __shared__ char smc[];
    const uint32_t sb = smem_u32(smc);

    const int tid = threadIdx.x;
    const int wid = tid >> 5;
    const int lane = tid & 31;
    const int bm = blockIdx.y * GBM;
    const int bn = blockIdx.x * GBN;

    // ---- cp.async load mapping: thread -> (row, 2 chunks of 16B) ----
    const int lr = tid >> 1;             // 0..127
    const int lc = (tid & 1) * 2;        // chunk 0 or 2
    const __nv_bfloat16* gAh = Ah + (size_t)(bm + lr) * DD + lc * 8;
    const __nv_bfloat16* gAl = Al + (size_t)(bm + lr) * DD + lc * 8;
    const __nv_bfloat16* gBh = Bh + (size_t)(bn + lr) * DD + lc * 8;
    const __nv_bfloat16* gBl = Bl + (size_t)(bn + lr) * DD + lc * 8;
    const uint32_t so0 = swz(lr, lc);
    const uint32_t so1 = swz(lr, lc + 1);

    // ---- warp tiling: 4(M) x 2(N); warp tile 32x64 ----
    const int wm = (wid & 3) * 32;
    const int wn = (wid >> 2) * 64;

    float acc[2][8][4];
#pragma unroll
    for (int i = 0; i < 2; i++)
#pragma unroll
        for (int j = 0; j < 8; j++)
#pragma unroll
            for (int q = 0; q < 4; q++) acc[i][j][q] = 0.f;

    // issue stage 0
    {
        const uint32_t st = sb;
        CP16(st + so0,          gAh);      CP16(st + so1,          gAh + 8);
        CP16(st + 8192  + so0,  gAl);      CP16(st + 8192  + so1,  gAl + 8);
        CP16(st + 16384 + so0,  gBh);      CP16(st + 16384 + so1,  gBh + 8);
        CP16(st + 24576 + so0,  gBl);      CP16(st + 24576 + so1,  gBl + 8);
        CP_COMMIT();
    }

    for (int it = 0; it < NIT; ++it) {
        if (it + 1 < NIT) {
            const uint32_t st = sb + ((it + 1) & 1) * STAGE_BYTES;
            const int koff = (it + 1) * GBK;
            CP16(st + so0,          gAh + koff);  CP16(st + so1,          gAh + koff + 8);
            CP16(st + 8192  + so0,  gAl + koff);  CP16(st + 8192  + so1,  gAl + koff + 8);
            CP16(st + 16384 + so0,  gBh + koff);  CP16(st + 16384 + so1,  gBh + koff + 8);
            CP16(st + 24576 + so0,  gBl + koff);  CP16(st + 24576 + so1,  gBl + koff + 8);
            CP_COMMIT();
            CP_WAIT(1);
        } else {
            CP_WAIT(0);
        }
        __syncthreads();

        const uint32_t st = sb + (it & 1) * STAGE_BYTES;
        const uint32_t sAh = st;
        const uint32_t sAl = st + 8192;
        const uint32_t sBh = st + 16384;
        const uint32_t sBl = st + 24576;

#pragma unroll
        for (int s = 0; s < 2; s++) {
            const int c = s * 2 + (lane >> 4);        // chunk for this lane
            // A fragments (2 m-tiles, hi+lo)
            uint32_t ah[2][4], al[2][4];
#pragma unroll
            for (int i = 0; i < 2; i++) {
                const int r = wm + i * 16 + (lane & 15);
                const uint32_t off = swz(r, c);
                LDSM_X4(ah[i], sAh + off);
                LDSM_X4(al[i], sAl + off);
            }
            // B fragments (8 n-tiles via 4 x4-ldmatrix, hi+lo)
            uint32_t bh[8][2], bl[8][2];
#pragma unroll
            for (int j2 = 0; j2 < 4; j2++) {
                const int n = wn + j2 * 16 + (lane & 15);
                const uint32_t off = swz(n, c);
                uint32_t t[4];
                LDSM_X4(t, sBh + off);
                bh[2 * j2][0] = t[0]; bh[2 * j2][1] = t[2];
                bh[2 * j2 + 1][0] = t[1]; bh[2 * j2 + 1][1] = t[3];
                LDSM_X4(t, sBl + off);
                bl[2 * j2][0] = t[0]; bl[2 * j2][1] = t[2];
                bl[2 * j2 + 1][0] = t[1]; bl[2 * j2 + 1][1] = t[3];
            }
#pragma unroll
            for (int i = 0; i < 2; i++)
#pragma unroll
                for (int j = 0; j < 8; j++) {
                    MMA_BF16(acc[i][j], ah[i], bh[j]);
                    MMA_BF16(acc[i][j], ah[i], bl[j]);
                    MMA_BF16(acc[i][j], al[i], bh[j]);
                }
        }
        __syncthreads();
    }

    // ---- epilogue: bias + store (optionally split-head layout) ----
    const int lrow = lane >> 2;          // 0..7
    const int lcol = (lane & 3) * 2;     // 0,2,4,6
#pragma unroll
    for (int i = 0; i < 2; i++) {
#pragma unroll
        for (int j = 0; j < 8; j++) {
            const int col = bn + wn + j * 8 + lcol;
            const float b0 = __ldg(&bias[col]);
            const float b1 = __ldg(&bias[col + 1]);
#pragma unroll
            for (int half = 0; half < 2; half++) {
                const int m = bm + wm + i * 16 + lrow + half * 8;
                float2 v;
                v.x = acc[i][j][2 * half + 0] + b0;
                v.y = acc[i][j][2 * half + 1] + b1;
                if (split_heads) {
                    const int bb = m >> 11;
                    const int s = m & 2047;
                    const int h = col >> 6;
                    const int dk = col & 63;
                    *(float2*)&C[(((size_t)(bb * HH + h)) * SS + s) * DKH + dk] = v;
                } else {
                    *(float2*)&C[(size_t)m * DD + col] = v;
                }
            }
        }
    }
}

// =====================================================================
// Flash attention, causal (SIMT fp32 — unchanged from round 1).
// =====================================================================
__global__ __launch_bounds__(256, 2) void attn_kernel(
    const float* __restrict__ Q, const float* __restrict__ K,
    const float* __restrict__ V, float* __restrict__ Out)
{
    extern __shared__ float smf[];
    float* Qt = smf;
    float* KP = smf + 64 * 128;
    float* Vs = KP + 64 * 128;

    const int tid = threadIdx.x;
    const int tx = tid & 15;
    const int ty = tid >> 4;
    const int qt = (SS / BQ - 1) - (int)blockIdx.x;
    const int bh = blockIdx.y;

    const float* Qg = Q + (size_t)bh * SS * DKH + (size_t)qt * BQ * DKH;
    const float* Kg = K + (size_t)bh * SS * DKH;
    const float* Vg = V + (size_t)bh * SS * DKH;

#pragma unroll
    for (int t = 0; t < 8; t++) {
        int idx = tid + t * 256;
        int r = idx >> 4;
        int d4 = (idx & 15) << 2;
        float4 v = *(const float4*)(Qg + (size_t)r * DKH + d4);
        Qt[(d4 + 0) * 128 + (r ^ ((d4 + 0) & 28))] = v.x * 0.125f;
        Qt[(d4 + 1) * 128 + (r ^ ((d4 + 1) & 28))] = v.y * 0.125f;
        Qt[(d4 + 2) * 128 + (r ^ ((d4 + 2) & 28))] = v.z * 0.125f;
        Qt[(d4 + 3) * 128 + (r ^ ((d4 + 3) & 28))] = v.w * 0.125f;
    }

    float O[8][4];
    float mrow[8], lrow[8];
#pragma unroll
    for (int i = 0; i < 8; i++) {
        mrow[i] = -1e30f; lrow[i] = 0.f;
#pragma unroll
        for (int j = 0; j < 4; j++) O[i][j] = 0.f;
    }

    const int nkt = 2 * qt + 2;
    for (int kt = 0; kt < nkt; kt++) {
#pragma unroll
        for (int t = 0; t < 4; t++) {
            int idx = tid + t * 256;
            int c = idx >> 4;
            int d4 = (idx & 15) << 2;
            float4 kv = *(const float4*)(Kg + (size_t)(kt * BKV + c) * DKH + d4);
            KP[(d4 + 0) * 64 + (c ^ ((d4 + 0) & 28))] = kv.x;
            KP[(d4 + 1) * 64 + (c ^ ((d4 + 1) & 28))] = kv.y;
            KP[(d4 + 2) * 64 + (c ^ ((d4 + 2) & 28))] = kv.z;
            KP[(d4 + 3) * 64 + (c ^ ((d4 + 3) & 28))] = kv.w;
            float4 vv = *(const float4*)(Vg + (size_t)(kt * BKV + c) * DKH + d4);
            *(float4*)&Vs[c * 64 + d4] = vv;
        }
        __syncthreads();

        float sc[8][4];
#pragma unroll
        for (int i = 0; i < 8; i++)
#pragma unroll
            for (int j = 0; j < 4; j++) sc[i][j] = 0.f;

#pragma unroll 8
        for (int d = 0; d < 64; d++) {
            const int kq = d & 28;
            float a[8], b[4];
            *(float4*)&a[0] = *(const float4*)&Qt[d * 128 + ((8 * ty) ^ kq)];
            *(float4*)&a[4] = *(const float4*)&Qt[d * 128 + ((8 * ty + 4) ^ kq)];
            *(float4*)&b[0] = *(const float4*)&KP[d * 64 + ((4 * tx) ^ kq)];
#pragma unroll
            for (int i = 0; i < 8; i++)
#pragma unroll
                for (int j = 0; j < 4; j++)
                    sc[i][j] = fmaf(a[i], b[j], sc[i][j]);
        }

        if (kt >= 2 * qt) {
            const int qbase = qt * BQ + 8 * ty;
            const int kbase = kt * BKV + 4 * tx;
#pragma unroll
            for (int i = 0; i < 8; i++)
#pragma unroll
                for (int j = 0; j < 4; j++)
                    if (kbase + j > qbase + i) sc[i][j] = -1e30f;
        }

#pragma unroll
        for (int i = 0; i < 8; i++) {
            float t = fmaxf(fmaxf(sc[i][0], sc[i][1]), fmaxf(sc[i][2], sc[i][3]));
            t = fmaxf(t, __shfl_xor_sync(0xffffffffu, t, 8));
            t = fmaxf(t, __shfl_xor_sync(0xffffffffu, t, 4));
            t = fmaxf(t, __shfl_xor_sync(0xffffffffu, t, 2));
            t = fmaxf(t, __shfl_xor_sync(0xffffffffu, t, 1));
            const float mnew = fmaxf(mrow[i], t);
            const float escf = __expf(mrow[i] - mnew);
            float rs = 0.f;
#pragma unroll
            for (int j = 0; j < 4; j++) {
                sc[i][j] = __expf(sc[i][j] - mnew);
                rs += sc[i][j];
            }
            rs += __shfl_xor_sync(0xffffffffu, rs, 8);
            rs += __shfl_xor_sync(0xffffffffu, rs, 4);
            rs += __shfl_xor_sync(0xffffffffu, rs, 2);
            rs += __shfl_xor_sync(0xffffffffu, rs, 1);
            lrow[i] = lrow[i] * escf + rs;
            mrow[i] = mnew;
#pragma unroll
            for (int j = 0; j < 4; j++) O[i][j] *= escf;
        }

        __syncthreads();

#pragma unroll
        for (int j = 0; j < 4; j++) {
            const int c = 4 * tx + j;
            const int cs = c & 28;
            float* prow = &KP[c * 128];
#pragma unroll
            for (int i = 0; i < 8; i++)
                prow[(8 * ty + i) ^ cs] = sc[i][j];
        }
        __syncthreads();

#pragma unroll 8
        for (int c = 0; c < 64; c++) {
            const int kc = c & 28;
            float a[8], b[4];
            *(float4*)&a[0] = *(const float4*)&KP[c * 128 + ((8 * ty) ^ kc)];
            *(float4*)&a[4] = *(const float4*)&KP[c * 128 + ((8 * ty + 4) ^ kc)];
            *(float4*)&b[0] = *(const float4*)&Vs[c * 64 + 4 * tx];
#pragma unroll
            for (int i = 0; i < 8; i++)
#pragma unroll
                for (int j = 0; j < 4; j++)
                    O[i][j] = fmaf(a[i], b[j], O[i][j]);
        }
        __syncthreads();
    }

    const int b = bh >> 4;
    const int h = bh & 15;
#pragma unroll
    for (int i = 0; i < 8; i++) {
        const int q = qt * BQ + 8 * ty + i;
        const float inv = 1.f / lrow[i];
        float4 v;
        v.x = O[i][0] * inv; v.y = O[i][1] * inv;
        v.z = O[i][2] * inv; v.w = O[i][3] * inv;
        *(float4*)&Out[((size_t)(b * SS + q)) * DD + h * DKH + 4 * tx] = v;
    }
}

// =====================================================================
extern "C" void kernel_launch(void* const* d_in, const int* in_sizes, int n_in,
                              void* d_out, int out_size)
{
    (void)in_sizes; (void)n_in; (void)out_size;
    const float* x  = (const float*)d_in[0];
    const float* Wq = (const float*)d_in[2];
    const float* bq = (const float*)d_in[3];
    const float* Wk = (const float*)d_in[4];
    const float* bk = (const float*)d_in[5];
    const float* Wv = (const float*)d_in[6];
    const float* bv = (const float*)d_in[7];
    const float* Wo = (const float*)d_in[8];
    const float* bo = (const float*)d_in[9];
    float* out = (float*)d_out;

    float *qp, *kp, *vp, *ap;
    __nv_bfloat16 *xh, *xl, *ah, *al, *wth, *wtl;
    cudaGetSymbolAddress((void**)&qp, g_Q);
    cudaGetSymbolAddress((void**)&kp, g_K);
    cudaGetSymbolAddress((void**)&vp, g_V);
    cudaGetSymbolAddress((void**)&ap, g_attn);
    cudaGetSymbolAddress((void**)&xh, g_xh);
    cudaGetSymbolAddress((void**)&xl, g_xl);
    cudaGetSymbolAddress((void**)&ah, g_ah);
    cudaGetSymbolAddress((void**)&al, g_al);
    cudaGetSymbolAddress((void**)&wth, g_Wth);
    cudaGetSymbolAddress((void**)&wtl, g_Wtl);

    cudaFuncSetAttribute(attn_kernel,
                         cudaFuncAttributeMaxDynamicSharedMemorySize,
                         ATTN_SMEM_BYTES);
    cudaFuncSetAttribute(gemm_mma_kernel,
                         cudaFuncAttributeMaxDynamicSharedMemorySize,
                         GEMM_SMEM_BYTES);

    const int n4 = MM * DD / 4;
    const dim3 tg(32, 32);
    const dim3 tb(32, 8);
    const dim3 gg(DD / GBN, MM / GBM);   // (8, 64)

    // prepass: split x, transpose+split weights
    split_bf16_kernel<<<(n4 + 255) / 256, 256>>>(x, xh, xl, n4);
    transpose_split_kernel<<<tg, tb>>>(Wq, wth + 0 * (size_t)DD * DD, wtl + 0 * (size_t)DD * DD);
    transpose_split_kernel<<<tg, tb>>>(Wk, wth + 1 * (size_t)DD * DD, wtl + 1 * (size_t)DD * DD);
    transpose_split_kernel<<<tg, tb>>>(Wv, wth + 2 * (size_t)DD * DD, wtl + 2 * (size_t)DD * DD);
    transpose_split_kernel<<<tg, tb>>>(Wo, wth + 3 * (size_t)DD * DD, wtl + 3 * (size_t)DD * DD);

    // QKV projections (tensor cores via mma.sync)
    gemm_mma_kernel<<<gg, 256, GEMM_SMEM_BYTES>>>(xh, xl, wth + 0 * (size_t)DD * DD, wtl + 0 * (size_t)DD * DD, bq, qp, 1);
    gemm_mma_kernel<<<gg, 256, GEMM_SMEM_BYTES>>>(xh, xl, wth + 1 * (size_t)DD * DD, wtl + 1 * (size_t)DD * DD, bk, kp, 1);
    gemm_mma_kernel<<<gg, 256, GEMM_SMEM_BYTES>>>(xh, xl, wth + 2 * (size_t)DD * DD, wtl + 2 * (size_t)DD * DD, bv, vp, 1);

    // attention
    attn_kernel<<<dim3(SS / BQ, BB * HH), 256, ATTN_SMEM_BYTES>>>(qp, kp, vp, ap);

    // output projection
    split_bf16_kernel<<<(n4 + 255) / 256, 256>>>(ap, ah, al, n4);
    gemm_mma_kernel<<<gg, 256, GEMM_SMEM_BYTES>>>(ah, al, wth + 3 * (size_t)DD * DD, wtl + 3 * (size_t)DD * DD, bo, out, 0);
}

// round 5
// speedup vs baseline: 2.7242x; 1.8765x over previous
#include <cuda_runtime.h>
#include <cuda_bf16.h>
#include <cstdint>

#define BB 4
#define SS 2048
#define DD 1024
#define HH 16
#define DKH 64
#define MM (BB * SS)   // 8192

// GEMM (HMMA) config: CTA 128x128, BK=32, double-buffered
#define GBM 128
#define GBN 128
#define GBK 32
#define STAGE_BYTES (4 * GBM * GBK * 2)      // Ah,Al,Bh,Bl tiles = 32 KB
#define GEMM_SMEM_BYTES (2 * STAGE_BYTES)    // 64 KB
#define NIT (DD / GBK)                       // 32

// Attention (HMMA) config
#define AQ 128
#define AKV 64
#define ATTN_SMEM_BYTES 65536    // Qh,Ql(16K each) + Kh,Kl,Vh,Vl(8K each)

// ---------------- scratch (device globals: allocation-free rule) ----------------
__device__ float g_Q[(size_t)MM * DD];
__device__ float g_K[(size_t)MM * DD];
__device__ float g_V[(size_t)MM * DD];
__device__ float g_attn[(size_t)MM * DD];
__device__ __nv_bfloat16 g_xh[(size_t)MM * DD];
__device__ __nv_bfloat16 g_xl[(size_t)MM * DD];
__device__ __nv_bfloat16 g_ah[(size_t)MM * DD];
__device__ __nv_bfloat16 g_al[(size_t)MM * DD];
__device__ __nv_bfloat16 g_Wth[4][(size_t)DD * DD];  // W^T hi, [n][k] (q,k,v,o contiguous)
__device__ __nv_bfloat16 g_Wtl[4][(size_t)DD * DD];  // W^T lo

// ---------------- PTX helpers ----------------
__device__ __forceinline__ uint32_t smem_u32(const void* p) {
    uint32_t a;
    asm("{ .reg .u64 t; cvta.to.shared.u64 t, %1; cvt.u32.u64 %0, t; }"
        : "=r"(a) : "l"(p));
    return a;
}

#define LDSM_X4(r, addr) \
    asm volatile("ldmatrix.sync.aligned.m8n8.x4.shared.b16 {%0,%1,%2,%3}, [%4];" \
                 : "=r"((r)[0]), "=r"((r)[1]), "=r"((r)[2]), "=r"((r)[3]) : "r"(addr))

#define LDSM_X4_T(r, addr) \
    asm volatile("ldmatrix.sync.aligned.m8n8.x4.trans.shared.b16 {%0,%1,%2,%3}, [%4];" \
                 : "=r"((r)[0]), "=r"((r)[1]), "=r"((r)[2]), "=r"((r)[3]) : "r"(addr))

#define MMA_BF16(d, a, b0, b1) \
    asm volatile("mma.sync.aligned.m16n8k16.row.col.f32.bf16.bf16.f32 " \
                 "{%0,%1,%2,%3}, {%4,%5,%6,%7}, {%8,%9}, {%0,%1,%2,%3};" \
                 : "+f"((d)[0]), "+f"((d)[1]), "+f"((d)[2]), "+f"((d)[3]) \
                 : "r"((a)[0]), "r"((a)[1]), "r"((a)[2]), "r"((a)[3]), \
                   "r"(b0), "r"(b1))

#define CP16(saddr, gptr) \
    asm volatile("cp.async.cg.shared.global [%0], [%1], 16;" \
                 :: "r"(saddr), "l"(gptr))
#define CP_COMMIT() asm volatile("cp.async.commit_group;" ::: "memory")
#define CP_WAIT(n)  asm volatile("cp.async.wait_group %0;" :: "n"(n) : "memory")

// GEMM tile swizzle: [128 rows][32 bf16], row pitch 64B, 4 chunks of 16B
__device__ __forceinline__ uint32_t swz(int r, int c) {
    return (uint32_t)(r * 64 + ((c ^ ((r >> 1) & 3)) << 4));
}
// Attention tile swizzle: [rows][64 bf16], row pitch 128B, 8 chunks of 16B
__device__ __forceinline__ uint32_t aswz(int r, int c) {
    return (uint32_t)(r * 128 + ((c ^ (r & 7)) << 4));
}

__device__ __forceinline__ uint32_t pack_bf16(float a, float b) {
    __nv_bfloat162 t = __floats2bfloat162_rn(a, b);   // x=a(lo), y=b(hi)
    return *(uint32_t*)&t;
}
__device__ __forceinline__ uint32_t pack_resid(float a, float b, uint32_t hp) {
    __nv_bfloat162 h = *(__nv_bfloat162*)&hp;
    return pack_bf16(a - __bfloat162float(h.x), b - __bfloat162float(h.y));
}

// read 8 consecutive f32, scale, emit hi(8 bf16) + lo residual as uint4
__device__ __forceinline__ void split8(const float* g, float scale,
                                       uint4& hd, uint4& ld) {
    float4 v0 = *(const float4*)g;
    float4 v1 = *(const float4*)(g + 4);
    v0.x *= scale; v0.y *= scale; v0.z *= scale; v0.w *= scale;
    v1.x *= scale; v1.y *= scale; v1.z *= scale; v1.w *= scale;
    hd.x = pack_bf16(v0.x, v0.y); hd.y = pack_bf16(v0.z, v0.w);
    hd.z = pack_bf16(v1.x, v1.y); hd.w = pack_bf16(v1.z, v1.w);
    ld.x = pack_resid(v0.x, v0.y, hd.x); ld.y = pack_resid(v0.z, v0.w, hd.y);
    ld.z = pack_resid(v1.x, v1.y, hd.z); ld.w = pack_resid(v1.z, v1.w, hd.w);
}

// =====================================================================
// split fp32 -> bf16 hi + bf16 lo (residual)
// =====================================================================
__global__ void split_bf16_kernel(const float* __restrict__ in,
                                  __nv_bfloat16* __restrict__ hi,
                                  __nv_bfloat16* __restrict__ lo, int n4)
{
    int i = blockIdx.x * blockDim.x + threadIdx.x;
    if (i >= n4) return;
    float4 v = ((const float4*)in)[i];
    uint32_t h0 = pack_bf16(v.x, v.y), h1 = pack_bf16(v.z, v.w);
    uint32_t l0 = pack_resid(v.x, v.y, h0), l1 = pack_resid(v.z, v.w, h1);
    ((uint2*)hi)[i] = make_uint2(h0, h1);
    ((uint2*)lo)[i] = make_uint2(l0, l1);
}

// =====================================================================
// W[k][n] fp32 -> Wt_hi[n][k], Wt_lo[n][k] bf16 (transpose + split)
// =====================================================================
__global__ void transpose_split_kernel(const float* __restrict__ W,
                                       __nv_bfloat16* __restrict__ Th,
                                       __nv_bfloat16* __restrict__ Tl)
{
    __shared__ float s[32][33];
    const int tx = threadIdx.x, ty = threadIdx.y;
    const int x0 = blockIdx.x * 32, y0 = blockIdx.y * 32;
#pragma unroll
    for (int j = 0; j < 32; j += 8)
        s[ty + j][tx] = W[(size_t)(y0 + ty + j) * DD + x0 + tx];
    __syncthreads();
#pragma unroll
    for (int j = 0; j < 32; j += 8) {
        float v = s[tx][ty + j];
        __nv_bfloat16 h = __float2bfloat16(v);
        __nv_bfloat16 l = __float2bfloat16(v - __bfloat162float(h));
        size_t o = (size_t)(x0 + ty + j) * DD + y0 + tx;
        Th[o] = h; Tl[o] = l;
    }
}

// =====================================================================
// Tensor-core GEMM via mma.sync: C = (Ah+Al) @ (Bh+Bl)^T + bias.
// Merged-N: B may have up to 3072 rows (QKV weights contiguous);
// bias/output selected per 1024-column project slab.
// =====================================================================
__global__ __launch_bounds__(256, 2) void gemm_mma_kernel(
    const __nv_bfloat16* __restrict__ Ah, const __nv_bfloat16* __restrict__ Al,
    const __nv_bfloat16* __restrict__ Bh, const __nv_bfloat16* __restrict__ Bl,
    const float* __restrict__ bias0, const float* __restrict__ bias1,
    const float* __restrict__ bias2,
    float* __restrict__ C0, float* __restrict__ C1, float* __restrict__ C2,
    int split_heads)
{
    extern __shared__ char smc[];
    const uint32_t sb = smem_u32(smc);

    const int tid = threadIdx.x;
    const int wid = tid >> 5;
    const int lane = tid & 31;
    const int bm = blockIdx.y * GBM;
    const int bn = blockIdx.x * GBN;          // 0..3071 (merged)
    const int proj = bn >> 10;
    const int bnl = bn & 1023;
    const float* bias = proj == 0 ? bias0 : (proj == 1 ? bias1 : bias2);
    float* C = proj == 0 ? C0 : (proj == 1 ? C1 : C2);

    // cp.async mapping
    const int lr = tid >> 1;
    const int lc = (tid & 1) * 2;
    const __nv_bfloat16* gAh = Ah + (size_t)(bm + lr) * DD + lc * 8;
    const __nv_bfloat16* gAl = Al + (size_t)(bm + lr) * DD + lc * 8;
    const __nv_bfloat16* gBh = Bh + (size_t)(bn + lr) * DD + lc * 8;
    const __nv_bfloat16* gBl = Bl + (size_t)(bn + lr) * DD + lc * 8;
    const uint32_t so0 = swz(lr, lc);
    const uint32_t so1 = swz(lr, lc + 1);

    const int wm = (wid & 3) * 32;
    const int wn = (wid >> 2) * 64;

    float acc[2][8][4];
#pragma unroll
    for (int i = 0; i < 2; i++)
#pragma unroll
        for (int j = 0; j < 8; j++)
#pragma unroll
            for (int q = 0; q < 4; q++) acc[i][j][q] = 0.f;

    {
        const uint32_t st = sb;
        CP16(st + so0,          gAh);      CP16(st + so1,          gAh + 8);
        CP16(st + 8192  + so0,  gAl);      CP16(st + 8192  + so1,  gAl + 8);
        CP16(st + 16384 + so0,  gBh);      CP16(st + 16384 + so1,  gBh + 8);
        CP16(st + 24576 + so0,  gBl);      CP16(st + 24576 + so1,  gBl + 8);
        CP_COMMIT();
    }

    for (int it = 0; it < NIT; ++it) {
        if (it + 1 < NIT) {
            const uint32_t st = sb + ((it + 1) & 1) * STAGE_BYTES;
            const int koff = (it + 1) * GBK;
            CP16(st + so0,          gAh + koff);  CP16(st + so1,          gAh + koff + 8);
            CP16(st + 8192  + so0,  gAl + koff);  CP16(st + 8192  + so1,  gAl + koff + 8);
            CP16(st + 16384 + so0,  gBh + koff);  CP16(st + 16384 + so1,  gBh + koff + 8);
            CP16(st + 24576 + so0,  gBl + koff);  CP16(st + 24576 + so1,  gBl + koff + 8);
            CP_COMMIT();
            CP_WAIT(1);
        } else {
            CP_WAIT(0);
        }
        __syncthreads();

        const uint32_t st = sb + (it & 1) * STAGE_BYTES;
        const uint32_t sAh = st, sAl = st + 8192, sBh = st + 16384, sBl = st + 24576;

#pragma unroll
        for (int s = 0; s < 2; s++) {
            const int c = s * 2 + (lane >> 4);
            uint32_t ah[2][4], al[2][4];
#pragma unroll
            for (int i = 0; i < 2; i++) {
                const uint32_t off = swz(wm + i * 16 + (lane & 15), c);
                LDSM_X4(ah[i], sAh + off);
                LDSM_X4(al[i], sAl + off);
            }
#pragma unroll
            for (int j2 = 0; j2 < 4; j2++) {
                const uint32_t off = swz(wn + j2 * 16 + (lane & 15), c);
                uint32_t t0[4], t1[4];
                LDSM_X4(t0, sBh + off);
                LDSM_X4(t1, sBl + off);
#pragma unroll
                for (int i = 0; i < 2; i++) {
                    MMA_BF16(acc[i][2 * j2],     ah[i], t0[0], t0[2]);
                    MMA_BF16(acc[i][2 * j2],     ah[i], t1[0], t1[2]);
                    MMA_BF16(acc[i][2 * j2],     al[i], t0[0], t0[2]);
                    MMA_BF16(acc[i][2 * j2 + 1], ah[i], t0[1], t0[3]);
                    MMA_BF16(acc[i][2 * j2 + 1], ah[i], t1[1], t1[3]);
                    MMA_BF16(acc[i][2 * j2 + 1], al[i], t0[1], t0[3]);
                }
            }
        }
        __syncthreads();
    }

    // epilogue
    const int lrow = lane >> 2;
    const int lcol = (lane & 3) * 2;
#pragma unroll
    for (int i = 0; i < 2; i++) {
#pragma unroll
        for (int j = 0; j < 8; j++) {
            const int col = bnl + wn + j * 8 + lcol;   // 0..1023 local
            const float b0 = __ldg(&bias[col]);
            const float b1 = __ldg(&bias[col + 1]);
#pragma unroll
            for (int half = 0; half < 2; half++) {
                const int m = bm + wm + i * 16 + lrow + half * 8;
                float2 v;
                v.x = acc[i][j][2 * half + 0] + b0;
                v.y = acc[i][j][2 * half + 1] + b1;
                if (split_heads) {
                    const int bb = m >> 11;
                    const int s = m & 2047;
                    const int h = col >> 6;
                    const int dk = col & 63;
                    *(float2*)&C[(((size_t)(bb * HH + h)) * SS + s) * DKH + dk] = v;
                } else {
                    *(float2*)&C[(size_t)m * DD + col] = v;
                }
            }
        }
    }
}

// =====================================================================
// Flash attention via mma.sync, causal, split-bf16.
// CTA: 8 warps, 128 q-rows; warp w owns rows 16w..16w+15. KV tile = 64.
// smem: Qh,Ql [128][64]; Kh,Kl,Vh,Vl [64][64]  (bf16, aswz layout)
// =====================================================================
__global__ __launch_bounds__(256, 2) void attn_mma_kernel(
    const float* __restrict__ Q, const float* __restrict__ K,
    const float* __restrict__ V, float* __restrict__ Out)
{
    extern __shared__ char smb[];
    const uint32_t sb = smem_u32(smb);
    // byte offsets
    const uint32_t oQh = 0, oQl = 16384, oKh = 32768, oKl = 40960, oVh = 49152, oVl = 57344;

    const int tid = threadIdx.x;
    const int wid = tid >> 5;
    const int lane = tid & 31;
    const int qt = (SS / AQ - 1) - (int)blockIdx.x;   // heavy tiles first
    const int bh = blockIdx.y;

    const float* Qg = Q + (size_t)bh * SS * DKH + (size_t)qt * AQ * DKH;
    const float* Kg = K + (size_t)bh * SS * DKH;
    const float* Vg = V + (size_t)bh * SS * DKH;

    // ---- load Q (128x64 f32 -> split bf16, scaled by 1/8) ----
#pragma unroll
    for (int t = 0; t < 4; t++) {
        const int idx = tid + t * 256;          // 0..1023
        const int r = idx >> 3, c = idx & 7;
        uint4 h, l;
        split8(Qg + (size_t)r * DKH + c * 8, 0.125f, h, l);
        const uint32_t so = aswz(r, c);
        *(uint4*)(smb + oQh + so) = h;
        *(uint4*)(smb + oQl + so) = l;
    }

    float oacc[8][4];
#pragma unroll
    for (int j = 0; j < 8; j++)
#pragma unroll
        for (int q = 0; q < 4; q++) oacc[j][q] = 0.f;
    float mrow[2] = {-1e30f, -1e30f};
    float lrow[2] = {0.f, 0.f};

    const int wm = wid * 16;
    const int nkt = 2 * qt + 2;

    for (int kt = 0; kt < nkt; kt++) {
        __syncthreads();   // protect smem tiles from previous iteration readers
        // ---- load K,V tile (64x64 f32 each -> split bf16) ----
#pragma unroll
        for (int t = 0; t < 2; t++) {
            const int idx = tid + t * 256;      // 0..511
            const int r = idx >> 3, c = idx & 7;
            const uint32_t so = aswz(r, c);
            uint4 h, l;
            split8(Kg + (size_t)(kt * AKV + r) * DKH + c * 8, 1.f, h, l);
            *(uint4*)(smb + oKh + so) = h;
            *(uint4*)(smb + oKl + so) = l;
            split8(Vg + (size_t)(kt * AKV + r) * DKH + c * 8, 1.f, h, l);
            *(uint4*)(smb + oVh + so) = h;
            *(uint4*)(smb + oVl + so) = l;
        }
        __syncthreads();

        // ---- S = Q K^T (3-term split) ----
        float sacc[8][4];
#pragma unroll
        for (int j = 0; j < 8; j++)
#pragma unroll
            for (int q = 0; q < 4; q++) sacc[j][q] = 0.f;

#pragma unroll
        for (int s = 0; s < 4; s++) {
            const int c = 2 * s + (lane >> 4);
            uint32_t qh[4], ql[4];
            const uint32_t qoff = aswz(wm + (lane & 15), c);
            LDSM_X4(qh, sb + oQh + qoff);
            LDSM_X4(ql, sb + oQl + qoff);
#pragma unroll
            for (int j2 = 0; j2 < 4; j2++) {
                const uint32_t koff = aswz(16 * j2 + (lane & 15), c);
                uint32_t t0[4], t1[4];
                LDSM_X4(t0, sb + oKh + koff);
                LDSM_X4(t1, sb + oKl + koff);
                MMA_BF16(sacc[2 * j2],     qh, t0[0], t0[2]);
                MMA_BF16(sacc[2 * j2],     qh, t1[0], t1[2]);
                MMA_BF16(sacc[2 * j2],     ql, t0[0], t0[2]);
                MMA_BF16(sacc[2 * j2 + 1], qh, t0[1], t0[3]);
                MMA_BF16(sacc[2 * j2 + 1], qh, t1[1], t1[3]);
                MMA_BF16(sacc[2 * j2 + 1], ql, t0[1], t0[3]);
            }
        }

        // ---- causal mask (diagonal-crossing tiles only) ----
        if (kt >= 2 * qt) {
            const int rowg = qt * AQ + wm + (lane >> 2);
            const int colg = kt * AKV + 2 * (lane & 3);
#pragma unroll
            for (int j = 0; j < 8; j++)
#pragma unroll
                for (int q = 0; q < 4; q++) {
                    const int rr = rowg + (q >> 1) * 8;
                    const int cc = colg + j * 8 + (q & 1);
                    if (cc > rr) sacc[j][q] = -1e30f;
                }
        }

        // ---- online softmax (per lane: 2 rows, quad-reduced) ----
#pragma unroll
        for (int hf = 0; hf < 2; hf++) {
            float mx = -1e30f;
#pragma unroll
            for (int j = 0; j < 8; j++)
                mx = fmaxf(mx, fmaxf(sacc[j][2 * hf], sacc[j][2 * hf + 1]));
            mx = fmaxf(mx, __shfl_xor_sync(0xffffffffu, mx, 1));
            mx = fmaxf(mx, __shfl_xor_sync(0xffffffffu, mx, 2));
            const float mnew = fmaxf(mrow[hf], mx);
            const float escf = __expf(mrow[hf] - mnew);
            float rs = 0.f;
#pragma unroll
            for (int j = 0; j < 8; j++) {
                sacc[j][2 * hf]     = __expf(sacc[j][2 * hf] - mnew);
                sacc[j][2 * hf + 1] = __expf(sacc[j][2 * hf + 1] - mnew);
                rs += sacc[j][2 * hf] + sacc[j][2 * hf + 1];
            }
            rs += __shfl_xor_sync(0xffffffffu, rs, 1);
            rs += __shfl_xor_sync(0xffffffffu, rs, 2);
            lrow[hf] = lrow[hf] * escf + rs;
            mrow[hf] = mnew;
#pragma unroll
            for (int j = 0; j < 8; j++) {
                oacc[j][2 * hf]     *= escf;
                oacc[j][2 * hf + 1] *= escf;
            }
        }

        // ---- O += P @ V  (P from regs via C-frag->A-frag identity) ----
#pragma unroll
        for (int t = 0; t < 4; t++) {
            uint32_t ph[4], pl[4];
            ph[0] = pack_bf16(sacc[2 * t][0],     sacc[2 * t][1]);
            ph[1] = pack_bf16(sacc[2 * t][2],     sacc[2 * t][3]);
            ph[2] = pack_bf16(sacc[2 * t + 1][0], sacc[2 * t + 1][1]);
            ph[3] = pack_bf16(sacc[2 * t + 1][2], sacc[2 * t + 1][3]);
            pl[0] = pack_resid(sacc[2 * t][0],     sacc[2 * t][1],     ph[0]);
            pl[1] = pack_resid(sacc[2 * t][2],     sacc[2 * t][3],     ph[1]);
            pl[2] = pack_resid(sacc[2 * t + 1][0], sacc[2 * t + 1][1], ph[2]);
            pl[3] = pack_resid(sacc[2 * t + 1][2], sacc[2 * t + 1][3], ph[3]);

            const int r_ld = 16 * t + (lane & 7) + ((lane >> 3) & 1) * 8;
#pragma unroll
            for (int j2 = 0; j2 < 4; j2++) {
                const int c_ld = 2 * j2 + (lane >> 4);
                const uint32_t voff = aswz(r_ld, c_ld);
                uint32_t t0[4], t1[4];
                LDSM_X4_T(t0, sb + oVh + voff);
                LDSM_X4_T(t1, sb + oVl + voff);
                MMA_BF16(oacc[2 * j2],     ph, t0[0], t0[1]);
                MMA_BF16(oacc[2 * j2],     ph, t1[0], t1[1]);
                MMA_BF16(oacc[2 * j2],     pl, t0[0], t0[1]);
                MMA_BF16(oacc[2 * j2 + 1], ph, t0[2], t0[3]);
                MMA_BF16(oacc[2 * j2 + 1], ph, t1[2], t1[3]);
                MMA_BF16(oacc[2 * j2 + 1], pl, t0[2], t0[3]);
            }
        }
    }

    // ---- write combined-head layout [b, s, h*64+dk] ----
    const int b = bh >> 4;
    const int h = bh & 15;
    const int r0 = qt * AQ + wm + (lane >> 2);
    const float inv0 = 1.f / lrow[0];
    const float inv1 = 1.f / lrow[1];
#pragma unroll
    for (int j = 0; j < 8; j++) {
        const int dk = h * DKH + 8 * j + 2 * (lane & 3);
        float2 v0, v1;
        v0.x = oacc[j][0] * inv0; v0.y = oacc[j][1] * inv0;
        v1.x = oacc[j][2] * inv1; v1.y = oacc[j][3] * inv1;
        *(float2*)&Out[((size_t)(b * SS + r0)) * DD + dk] = v0;
        *(float2*)&Out[((size_t)(b * SS + r0 + 8)) * DD + dk] = v1;
    }
}

// =====================================================================
extern "C" void kernel_launch(void* const* d_in, const int* in_sizes, int n_in,
                              void* d_out, int out_size)
{
    (void)in_sizes; (void)n_in; (void)out_size;
    const float* x  = (const float*)d_in[0];
    const float* Wq = (const float*)d_in[2];
    const float* bq = (const float*)d_in[3];
    const float* Wk = (const float*)d_in[4];
    const float* bk = (const float*)d_in[5];
    const float* Wv = (const float*)d_in[6];
    const float* bv = (const float*)d_in[7];
    const float* Wo = (const float*)d_in[8];
    const float* bo = (const float*)d_in[9];
    float* out = (float*)d_out;

    float *qp, *kp, *vp, *ap;
    __nv_bfloat16 *xh, *xl, *ah, *al, *wth, *wtl;
    cudaGetSymbolAddress((void**)&qp, g_Q);
    cudaGetSymbolAddress((void**)&kp, g_K);
    cudaGetSymbolAddress((void**)&vp, g_V);
    cudaGetSymbolAddress((void**)&ap, g_attn);
    cudaGetSymbolAddress((void**)&xh, g_xh);
    cudaGetSymbolAddress((void**)&xl, g_xl);
    cudaGetSymbolAddress((void**)&ah, g_ah);
    cudaGetSymbolAddress((void**)&al, g_al);
    cudaGetSymbolAddress((void**)&wth, g_Wth);
    cudaGetSymbolAddress((void**)&wtl, g_Wtl);

    cudaFuncSetAttribute(attn_mma_kernel,
                         cudaFuncAttributeMaxDynamicSharedMemorySize,
                         ATTN_SMEM_BYTES);
    cudaFuncSetAttribute(gemm_mma_kernel,
                         cudaFuncAttributeMaxDynamicSharedMemorySize,
                         GEMM_SMEM_BYTES);

    const int n4 = MM * DD / 4;
    const dim3 tg(32, 32);
    const dim3 tb(32, 8);
    const size_t WSZ = (size_t)DD * DD;

    // prepass
    split_bf16_kernel<<<(n4 + 255) / 256, 256>>>(x, xh, xl, n4);
    transpose_split_kernel<<<tg, tb>>>(Wq, wth + 0 * WSZ, wtl + 0 * WSZ);
    transpose_split_kernel<<<tg, tb>>>(Wk, wth + 1 * WSZ, wtl + 1 * WSZ);
    transpose_split_kernel<<<tg, tb>>>(Wv, wth + 2 * WSZ, wtl + 2 * WSZ);
    transpose_split_kernel<<<tg, tb>>>(Wo, wth + 3 * WSZ, wtl + 3 * WSZ);

    // merged QKV projection: N=3072 (weights contiguous), split-head outputs
    gemm_mma_kernel<<<dim3(3 * DD / GBN, MM / GBM), 256, GEMM_SMEM_BYTES>>>(
        xh, xl, wth, wtl, bq, bk, bv, qp, kp, vp, 1);

    // attention (tensor cores)
    attn_mma_kernel<<<dim3(SS / AQ, BB * HH), 256, ATTN_SMEM_BYTES>>>(qp, kp, vp, ap);

    // output projection
    split_bf16_kernel<<<(n4 + 255) / 256, 256>>>(ap, ah, al, n4);
    gemm_mma_kernel<<<dim3(DD / GBN, MM / GBM), 256, GEMM_SMEM_BYTES>>>(
        ah, al, wth + 3 * WSZ, wtl + 3 * WSZ, bo, bo, bo, out, out, out, 0);
}

// round 6
// speedup vs baseline: 2.9541x; 1.0844x over previous
#include <cuda_runtime.h>
#include <cuda_bf16.h>
#include <cstdint>

#define BB 4
#define SS 2048
#define DD 1024
#define HH 16
#define DKH 64
#define MM (BB * SS)   // 8192

// GEMM (HMMA) config: CTA 128x128, BK=32, 3-stage cp.async ring
#define GBM 128
#define GBN 128
#define GBK 32
#define STAGE_BYTES (4 * GBM * GBK * 2)      // Ah,Al,Bh,Bl tiles = 32 KB
#define GEMM_STAGES 3
#define GEMM_SMEM_BYTES (GEMM_STAGES * STAGE_BYTES)   // 96 KB
#define NIT (DD / GBK)                       // 32

// Attention config: Q 128x64 resident, KV 64x64 double-buffered
#define AQ 128
#define AKV 64
#define KV_STAGE 32768                        // Kh,Kl,Vh,Vl = 4 x 8KB
#define ATTN_SMEM_BYTES (32768 + 2 * KV_STAGE)  // Qh,Ql + 2 KV stages = 96 KB

// ---------------- scratch (device globals: allocation-free rule) ----------------
__device__ __nv_bfloat16 g_Qh[(size_t)MM * DD];
__device__ __nv_bfloat16 g_Ql[(size_t)MM * DD];
__device__ __nv_bfloat16 g_Kh[(size_t)MM * DD];
__device__ __nv_bfloat16 g_Kl[(size_t)MM * DD];
__device__ __nv_bfloat16 g_Vh[(size_t)MM * DD];
__device__ __nv_bfloat16 g_Vl[(size_t)MM * DD];
__device__ __nv_bfloat16 g_xh[(size_t)MM * DD];
__device__ __nv_bfloat16 g_xl[(size_t)MM * DD];
__device__ __nv_bfloat16 g_ah[(size_t)MM * DD];
__device__ __nv_bfloat16 g_al[(size_t)MM * DD];
__device__ __nv_bfloat16 g_Wth[4][(size_t)DD * DD];
__device__ __nv_bfloat16 g_Wtl[4][(size_t)DD * DD];

// ---------------- PTX helpers ----------------
__device__ __forceinline__ uint32_t smem_u32(const void* p) {
    uint32_t a;
    asm("{ .reg .u64 t; cvta.to.shared.u64 t, %1; cvt.u32.u64 %0, t; }"
        : "=r"(a) : "l"(p));
    return a;
}

#define LDSM_X4(r, addr) \
    asm volatile("ldmatrix.sync.aligned.m8n8.x4.shared.b16 {%0,%1,%2,%3}, [%4];" \
                 : "=r"((r)[0]), "=r"((r)[1]), "=r"((r)[2]), "=r"((r)[3]) : "r"(addr))

#define LDSM_X4_T(r, addr) \
    asm volatile("ldmatrix.sync.aligned.m8n8.x4.trans.shared.b16 {%0,%1,%2,%3}, [%4];" \
                 : "=r"((r)[0]), "=r"((r)[1]), "=r"((r)[2]), "=r"((r)[3]) : "r"(addr))

#define MMA_BF16(d, a, b0, b1) \
    asm volatile("mma.sync.aligned.m16n8k16.row.col.f32.bf16.bf16.f32 " \
                 "{%0,%1,%2,%3}, {%4,%5,%6,%7}, {%8,%9}, {%0,%1,%2,%3};" \
                 : "+f"((d)[0]), "+f"((d)[1]), "+f"((d)[2]), "+f"((d)[3]) \
                 : "r"((a)[0]), "r"((a)[1]), "r"((a)[2]), "r"((a)[3]), \
                   "r"(b0), "r"(b1))

#define CP16(saddr, gptr) \
    asm volatile("cp.async.cg.shared.global [%0], [%1], 16;" \
                 :: "r"(saddr), "l"(gptr))
#define CP_COMMIT() asm volatile("cp.async.commit_group;" ::: "memory")
#define CP_WAIT(n)  asm volatile("cp.async.wait_group %0;" :: "n"(n) : "memory")

// GEMM tile swizzle: [128 rows][32 bf16], row pitch 64B, 4 chunks
__device__ __forceinline__ uint32_t swz(int r, int c) {
    return (uint32_t)(r * 64 + ((c ^ ((r >> 1) & 3)) << 4));
}
// Attention tile swizzle: [rows][64 bf16], row pitch 128B, 8 chunks
__device__ __forceinline__ uint32_t aswz(int r, int c) {
    return (uint32_t)(r * 128 + ((c ^ (r & 7)) << 4));
}

__device__ __forceinline__ uint32_t pack_bf16(float a, float b) {
    __nv_bfloat162 t = __floats2bfloat162_rn(a, b);
    return *(uint32_t*)&t;
}
__device__ __forceinline__ uint32_t pack_resid(float a, float b, uint32_t hp) {
    __nv_bfloat162 h = *(__nv_bfloat162*)&hp;
    return pack_bf16(a - __bfloat162float(h.x), b - __bfloat162float(h.y));
}

// =====================================================================
// split fp32 -> bf16 hi + lo (x prepass only)
// =====================================================================
__global__ void split_bf16_kernel(const float* __restrict__ in,
                                  __nv_bfloat16* __restrict__ hi,
                                  __nv_bfloat16* __restrict__ lo, int n4)
{
    int i = blockIdx.x * blockDim.x + threadIdx.x;
    if (i >= n4) return;
    float4 v = ((const float4*)in)[i];
    uint32_t h0 = pack_bf16(v.x, v.y), h1 = pack_bf16(v.z, v.w);
    uint32_t l0 = pack_resid(v.x, v.y, h0), l1 = pack_resid(v.z, v.w, h1);
    ((uint2*)hi)[i] = make_uint2(h0, h1);
    ((uint2*)lo)[i] = make_uint2(l0, l1);
}

// =====================================================================
// 4 weights at once: W[k][n] -> Wt hi/lo [n][k] (z = which weight)
// =====================================================================
__global__ void transpose_split_kernel(
    const float* __restrict__ W0, const float* __restrict__ W1,
    const float* __restrict__ W2, const float* __restrict__ W3,
    __nv_bfloat16* __restrict__ Th, __nv_bfloat16* __restrict__ Tl)
{
    __shared__ float s[32][33];
    const int z = blockIdx.z;
    const float* W = z == 0 ? W0 : (z == 1 ? W1 : (z == 2 ? W2 : W3));
    __nv_bfloat16* th = Th + (size_t)z * DD * DD;
    __nv_bfloat16* tl = Tl + (size_t)z * DD * DD;
    const int tx = threadIdx.x, ty = threadIdx.y;
    const int x0 = blockIdx.x * 32, y0 = blockIdx.y * 32;
#pragma unroll
    for (int j = 0; j < 32; j += 8)
        s[ty + j][tx] = W[(size_t)(y0 + ty + j) * DD + x0 + tx];
    __syncthreads();
#pragma unroll
    for (int j = 0; j < 32; j += 8) {
        float v = s[tx][ty + j];
        __nv_bfloat16 h = __float2bfloat16(v);
        __nv_bfloat16 l = __float2bfloat16(v - __bfloat162float(h));
        size_t o = (size_t)(x0 + ty + j) * DD + y0 + tx;
        th[o] = h; tl[o] = l;
    }
}

// =====================================================================
// Tensor-core GEMM, 3-stage cp.async ring, split-bf16 3-term.
// split_heads=1: writes split bf16 Q/K/V (Q pre-scaled 1/8), merged N=3072.
// split_heads=0: writes fp32 C (+bias).
// =====================================================================
__global__ __launch_bounds__(256, 2) void gemm_mma_kernel(
    const __nv_bfloat16* __restrict__ Ah, const __nv_bfloat16* __restrict__ Al,
    const __nv_bfloat16* __restrict__ Bh, const __nv_bfloat16* __restrict__ Bl,
    const float* __restrict__ bias0, const float* __restrict__ bias1,
    const float* __restrict__ bias2,
    __nv_bfloat16* __restrict__ H0, __nv_bfloat16* __restrict__ L0,
    __nv_bfloat16* __restrict__ H1, __nv_bfloat16* __restrict__ L1,
    __nv_bfloat16* __restrict__ H2, __nv_bfloat16* __restrict__ L2,
    float* __restrict__ C, int split_heads)
{
    extern __shared__ char smc[];
    const uint32_t sb = smem_u32(smc);

    const int tid = threadIdx.x;
    const int wid = tid >> 5;
    const int lane = tid & 31;
    const int bm = blockIdx.y * GBM;
    const int bn = blockIdx.x * GBN;
    const int proj = bn >> 10;
    const int bnl = bn & 1023;
    const float* bias = proj == 0 ? bias0 : (proj == 1 ? bias1 : bias2);

    const int lr = tid >> 1;
    const int lc = (tid & 1) * 2;
    const __nv_bfloat16* gAh = Ah + (size_t)(bm + lr) * DD + lc * 8;
    const __nv_bfloat16* gAl = Al + (size_t)(bm + lr) * DD + lc * 8;
    const __nv_bfloat16* gBh = Bh + (size_t)(bn + lr) * DD + lc * 8;
    const __nv_bfloat16* gBl = Bl + (size_t)(bn + lr) * DD + lc * 8;
    const uint32_t so0 = swz(lr, lc);
    const uint32_t so1 = swz(lr, lc + 1);

    const int wm = (wid & 3) * 32;
    const int wn = (wid >> 2) * 64;

    float acc[2][8][4];
#pragma unroll
    for (int i = 0; i < 2; i++)
#pragma unroll
        for (int j = 0; j < 8; j++)
#pragma unroll
            for (int q = 0; q < 4; q++) acc[i][j][q] = 0.f;

#define G_ISSUE(stg, koff) do {                                                  \
    const uint32_t st = sb + (stg) * STAGE_BYTES;                                \
    CP16(st + so0,          gAh + (koff));  CP16(st + so1,          gAh + (koff) + 8); \
    CP16(st + 8192  + so0,  gAl + (koff));  CP16(st + 8192  + so1,  gAl + (koff) + 8); \
    CP16(st + 16384 + so0,  gBh + (koff));  CP16(st + 16384 + so1,  gBh + (koff) + 8); \
    CP16(st + 24576 + so0,  gBl + (koff));  CP16(st + 24576 + so1,  gBl + (koff) + 8); \
    CP_COMMIT();                                                                 \
} while (0)

    G_ISSUE(0, 0);
    G_ISSUE(1, GBK);

    for (int it = 0; it < NIT; ++it) {
        if (it + 1 < NIT) { CP_WAIT(1); } else { CP_WAIT(0); }
        __syncthreads();

        const uint32_t st = sb + (it % GEMM_STAGES) * STAGE_BYTES;
        const uint32_t sAh = st, sAl = st + 8192, sBh = st + 16384, sBl = st + 24576;

#pragma unroll
        for (int s = 0; s < 2; s++) {
            const int c = s * 2 + (lane >> 4);
            uint32_t ah[2][4], al[2][4];
#pragma unroll
            for (int i = 0; i < 2; i++) {
                const uint32_t off = swz(wm + i * 16 + (lane & 15), c);
                LDSM_X4(ah[i], sAh + off);
                LDSM_X4(al[i], sAl + off);
            }
#pragma unroll
            for (int j2 = 0; j2 < 4; j2++) {
                const uint32_t off = swz(wn + j2 * 16 + (lane & 15), c);
                uint32_t t0[4], t1[4];
                LDSM_X4(t0, sBh + off);
                LDSM_X4(t1, sBl + off);
#pragma unroll
                for (int i = 0; i < 2; i++) {
                    MMA_BF16(acc[i][2 * j2],     ah[i], t0[0], t0[2]);
                    MMA_BF16(acc[i][2 * j2],     ah[i], t1[0], t1[2]);
                    MMA_BF16(acc[i][2 * j2],     al[i], t0[0], t0[2]);
                    MMA_BF16(acc[i][2 * j2 + 1], ah[i], t0[1], t0[3]);
                    MMA_BF16(acc[i][2 * j2 + 1], ah[i], t1[1], t1[3]);
                    MMA_BF16(acc[i][2 * j2 + 1], al[i], t0[1], t0[3]);
                }
            }
        }
        if (it + 2 < NIT)
            G_ISSUE((it + 2) % GEMM_STAGES, (it + 2) * GBK);
    }
#undef G_ISSUE

    // ---- epilogue ----
    __nv_bfloat16* Hh = proj == 0 ? H0 : (proj == 1 ? H1 : H2);
    __nv_bfloat16* Ll = proj == 0 ? L0 : (proj == 1 ? L1 : L2);
    const float sc = (split_heads && proj == 0) ? 0.125f : 1.f;
    const int lrow = lane >> 2;
    const int lcol = (lane & 3) * 2;
#pragma unroll
    for (int i = 0; i < 2; i++) {
#pragma unroll
        for (int j = 0; j < 8; j++) {
            const int col = bnl + wn + j * 8 + lcol;
            const float b0 = __ldg(&bias[col]);
            const float b1 = __ldg(&bias[col + 1]);
#pragma unroll
            for (int half = 0; half < 2; half++) {
                const int m = bm + wm + i * 16 + lrow + half * 8;
                float vx = (acc[i][j][2 * half + 0] + b0) * sc;
                float vy = (acc[i][j][2 * half + 1] + b1) * sc;
                if (split_heads) {
                    const int bb = m >> 11;
                    const int s = m & 2047;
                    const int h = col >> 6;
                    const int dk = col & 63;
                    const size_t off = ((((size_t)(bb * HH + h)) * SS + s) * DKH + dk) >> 1;
                    const uint32_t hp = pack_bf16(vx, vy);
                    ((uint32_t*)Hh)[off] = hp;
                    ((uint32_t*)Ll)[off] = pack_resid(vx, vy, hp);
                } else {
                    float2 v; v.x = vx; v.y = vy;
                    *(float2*)&C[(size_t)m * DD + col] = v;
                }
            }
        }
    }
}

// =====================================================================
// Flash attention via mma.sync, causal, pre-split bf16 in/out.
// Q resident, KV double-buffered via cp.async.
// Output: split bf16, combined-head layout.
// =====================================================================
__global__ __launch_bounds__(256, 2) void attn_mma_kernel(
    const __nv_bfloat16* __restrict__ Qh, const __nv_bfloat16* __restrict__ Ql,
    const __nv_bfloat16* __restrict__ Kh, const __nv_bfloat16* __restrict__ Kl,
    const __nv_bfloat16* __restrict__ Vh, const __nv_bfloat16* __restrict__ Vl,
    __nv_bfloat16* __restrict__ Oh, __nv_bfloat16* __restrict__ Ol)
{
    extern __shared__ char smb[];
    const uint32_t sb = smem_u32(smb);
    const uint32_t oQh = 0, oQl = 16384;

    const int tid = threadIdx.x;
    const int wid = tid >> 5;
    const int lane = tid & 31;
    const int qt = (SS / AQ - 1) - (int)blockIdx.x;
    const int bh = blockIdx.y;

    const size_t hb = (size_t)bh * SS * DKH;
    const __nv_bfloat16* Qgh = Qh + hb + (size_t)qt * AQ * DKH;
    const __nv_bfloat16* Qgl = Ql + hb + (size_t)qt * AQ * DKH;
    const __nv_bfloat16* Kgh = Kh + hb;
    const __nv_bfloat16* Kgl = Kl + hb;
    const __nv_bfloat16* Vgh = Vh + hb;
    const __nv_bfloat16* Vgl = Vl + hb;

    const int nkt = 2 * qt + 2;

#define KV_ISSUE(tile, stg) do {                                                \
    const uint32_t st = sb + 32768 + (stg) * KV_STAGE;                          \
    _Pragma("unroll")                                                           \
    for (int t = 0; t < 2; t++) {                                               \
        const int idx = tid + t * 256;                                          \
        const int r = idx >> 3, c = idx & 7;                                    \
        const uint32_t so = aswz(r, c);                                         \
        const size_t go = (size_t)((tile) * AKV + r) * DKH + c * 8;             \
        CP16(st + so,          Kgh + go);                                       \
        CP16(st + 8192  + so,  Kgl + go);                                       \
        CP16(st + 16384 + so,  Vgh + go);                                       \
        CP16(st + 24576 + so,  Vgl + go);                                       \
    }                                                                           \
    CP_COMMIT();                                                                \
} while (0)

    // prologue: Q + KV tile 0 as one group
#pragma unroll
    for (int t = 0; t < 4; t++) {
        const int idx = tid + t * 256;
        const int r = idx >> 3, c = idx & 7;
        const uint32_t so = aswz(r, c);
        const size_t go = (size_t)r * DKH + c * 8;
        CP16(sb + oQh + so, Qgh + go);
        CP16(sb + oQl + so, Qgl + go);
    }
    KV_ISSUE(0, 0);   // commit covers Q + KV0

    float oacc[8][4];
#pragma unroll
    for (int j = 0; j < 8; j++)
#pragma unroll
        for (int q = 0; q < 4; q++) oacc[j][q] = 0.f;
    float mrow[2] = {-1e30f, -1e30f};
    float lrow[2] = {0.f, 0.f};

    const int wm = wid * 16;

    for (int kt = 0; kt < nkt; kt++) {
        CP_WAIT(0);
        __syncthreads();
        if (kt + 1 < nkt) KV_ISSUE(kt + 1, (kt + 1) & 1);

        const uint32_t st = sb + 32768 + (kt & 1) * KV_STAGE;
        const uint32_t sKh = st, sKl = st + 8192, sVh = st + 16384, sVl = st + 24576;

        // ---- S = Q K^T ----
        float sacc[8][4];
#pragma unroll
        for (int j = 0; j < 8; j++)
#pragma unroll
            for (int q = 0; q < 4; q++) sacc[j][q] = 0.f;

#pragma unroll
        for (int s = 0; s < 4; s++) {
            const int c = 2 * s + (lane >> 4);
            uint32_t qh[4], ql[4];
            const uint32_t qoff = aswz(wm + (lane & 15), c);
            LDSM_X4(qh, sb + oQh + qoff);
            LDSM_X4(ql, sb + oQl + qoff);
#pragma unroll
            for (int j2 = 0; j2 < 4; j2++) {
                const uint32_t koff = aswz(16 * j2 + (lane & 15), c);
                uint32_t t0[4], t1[4];
                LDSM_X4(t0, sKh + koff);
                LDSM_X4(t1, sKl + koff);
                MMA_BF16(sacc[2 * j2],     qh, t0[0], t0[2]);
                MMA_BF16(sacc[2 * j2],     qh, t1[0], t1[2]);
                MMA_BF16(sacc[2 * j2],     ql, t0[0], t0[2]);
                MMA_BF16(sacc[2 * j2 + 1], qh, t0[1], t0[3]);
                MMA_BF16(sacc[2 * j2 + 1], qh, t1[1], t1[3]);
                MMA_BF16(sacc[2 * j2 + 1], ql, t0[1], t0[3]);
            }
        }

        // ---- causal mask ----
        if (kt >= 2 * qt) {
            const int rowg = qt * AQ + wm + (lane >> 2);
            const int colg = kt * AKV + 2 * (lane & 3);
#pragma unroll
            for (int j = 0; j < 8; j++)
#pragma unroll
                for (int q = 0; q < 4; q++) {
                    const int rr = rowg + (q >> 1) * 8;
                    const int cc = colg + j * 8 + (q & 1);
                    if (cc > rr) sacc[j][q] = -1e30f;
                }
        }

        // ---- online softmax ----
#pragma unroll
        for (int hf = 0; hf < 2; hf++) {
            float mx = -1e30f;
#pragma unroll
            for (int j = 0; j < 8; j++)
                mx = fmaxf(mx, fmaxf(sacc[j][2 * hf], sacc[j][2 * hf + 1]));
            mx = fmaxf(mx, __shfl_xor_sync(0xffffffffu, mx, 1));
            mx = fmaxf(mx, __shfl_xor_sync(0xffffffffu, mx, 2));
            const float mnew = fmaxf(mrow[hf], mx);
            const float escf = __expf(mrow[hf] - mnew);
            float rs = 0.f;
#pragma unroll
            for (int j = 0; j < 8; j++) {
                sacc[j][2 * hf]     = __expf(sacc[j][2 * hf] - mnew);
                sacc[j][2 * hf + 1] = __expf(sacc[j][2 * hf + 1] - mnew);
                rs += sacc[j][2 * hf] + sacc[j][2 * hf + 1];
            }
            rs += __shfl_xor_sync(0xffffffffu, rs, 1);
            rs += __shfl_xor_sync(0xffffffffu, rs, 2);
            lrow[hf] = lrow[hf] * escf + rs;
            mrow[hf] = mnew;
#pragma unroll
            for (int j = 0; j < 8; j++) {
                oacc[j][2 * hf]     *= escf;
                oacc[j][2 * hf + 1] *= escf;
            }
        }

        // ---- O += P @ V ----
#pragma unroll
        for (int t = 0; t < 4; t++) {
            uint32_t ph[4], pl[4];
            ph[0] = pack_bf16(sacc[2 * t][0],     sacc[2 * t][1]);
            ph[1] = pack_bf16(sacc[2 * t][2],     sacc[2 * t][3]);
            ph[2] = pack_bf16(sacc[2 * t + 1][0], sacc[2 * t + 1][1]);
            ph[3] = pack_bf16(sacc[2 * t + 1][2], sacc[2 * t + 1][3]);
            pl[0] = pack_resid(sacc[2 * t][0],     sacc[2 * t][1],     ph[0]);
            pl[1] = pack_resid(sacc[2 * t][2],     sacc[2 * t][3],     ph[1]);
            pl[2] = pack_resid(sacc[2 * t + 1][0], sacc[2 * t + 1][1], ph[2]);
            pl[3] = pack_resid(sacc[2 * t + 1][2], sacc[2 * t + 1][3], ph[3]);

            const int r_ld = 16 * t + (lane & 7) + ((lane >> 3) & 1) * 8;
#pragma unroll
            for (int j2 = 0; j2 < 4; j2++) {
                const int c_ld = 2 * j2 + (lane >> 4);
                const uint32_t voff = aswz(r_ld, c_ld);
                uint32_t t0[4], t1[4];
                LDSM_X4_T(t0, sVh + voff);
                LDSM_X4_T(t1, sVl + voff);
                MMA_BF16(oacc[2 * j2],     ph, t0[0], t0[1]);
                MMA_BF16(oacc[2 * j2],     ph, t1[0], t1[1]);
                MMA_BF16(oacc[2 * j2],     pl, t0[0], t0[1]);
                MMA_BF16(oacc[2 * j2 + 1], ph, t0[2], t0[3]);
                MMA_BF16(oacc[2 * j2 + 1], ph, t1[2], t1[3]);
                MMA_BF16(oacc[2 * j2 + 1], pl, t0[2], t0[3]);
            }
        }
    }
#undef KV_ISSUE

    // ---- epilogue: split bf16, combined-head layout ----
    const int b = bh >> 4;
    const int h = bh & 15;
    const int r0 = qt * AQ + wm + (lane >> 2);
    const float inv0 = 1.f / lrow[0];
    const float inv1 = 1.f / lrow[1];
#pragma unroll
    for (int j = 0; j < 8; j++) {
        const int dk = h * DKH + 8 * j + 2 * (lane & 3);
        const size_t o0 = (((size_t)(b * SS + r0)) * DD + dk) >> 1;
        const size_t o1 = (((size_t)(b * SS + r0 + 8)) * DD + dk) >> 1;
        float v0x = oacc[j][0] * inv0, v0y = oacc[j][1] * inv0;
        float v1x = oacc[j][2] * inv1, v1y = oacc[j][3] * inv1;
        uint32_t h0 = pack_bf16(v0x, v0y);
        uint32_t h1 = pack_bf16(v1x, v1y);
        ((uint32_t*)Oh)[o0] = h0;
        ((uint32_t*)Ol)[o0] = pack_resid(v0x, v0y, h0);
        ((uint32_t*)Oh)[o1] = h1;
        ((uint32_t*)Ol)[o1] = pack_resid(v1x, v1y, h1);
    }
}

// =====================================================================
extern "C" void kernel_launch(void* const* d_in, const int* in_sizes, int n_in,
                              void* d_out, int out_size)
{
    (void)in_sizes; (void)n_in; (void)out_size;
    const float* x  = (const float*)d_in[0];
    const float* Wq = (const float*)d_in[2];
    const float* bq = (const float*)d_in[3];
    const float* Wk = (const float*)d_in[4];
    const float* bk = (const float*)d_in[5];
    const float* Wv = (const float*)d_in[6];
    const float* bv = (const float*)d_in[7];
    const float* Wo = (const float*)d_in[8];
    const float* bo = (const float*)d_in[9];
    float* out = (float*)d_out;

    __nv_bfloat16 *qh, *ql, *kh, *kl, *vh, *vl, *xh, *xl, *ah, *al, *wth, *wtl;
    cudaGetSymbolAddress((void**)&qh, g_Qh);
    cudaGetSymbolAddress((void**)&ql, g_Ql);
    cudaGetSymbolAddress((void**)&kh, g_Kh);
    cudaGetSymbolAddress((void**)&kl, g_Kl);
    cudaGetSymbolAddress((void**)&vh, g_Vh);
    cudaGetSymbolAddress((void**)&vl, g_Vl);
    cudaGetSymbolAddress((void**)&xh, g_xh);
    cudaGetSymbolAddress((void**)&xl, g_xl);
    cudaGetSymbolAddress((void**)&ah, g_ah);
    cudaGetSymbolAddress((void**)&al, g_al);
    cudaGetSymbolAddress((void**)&wth, g_Wth);
    cudaGetSymbolAddress((void**)&wtl, g_Wtl);

    cudaFuncSetAttribute(attn_mma_kernel,
                         cudaFuncAttributeMaxDynamicSharedMemorySize,
                         ATTN_SMEM_BYTES);
    cudaFuncSetAttribute(gemm_mma_kernel,
                         cudaFuncAttributeMaxDynamicSharedMemorySize,
                         GEMM_SMEM_BYTES);

    const int n4 = MM * DD / 4;
    const size_t WSZ = (size_t)DD * DD;

    split_bf16_kernel<<<(n4 + 255) / 256, 256>>>(x, xh, xl, n4);
    transpose_split_kernel<<<dim3(32, 32, 4), dim3(32, 8)>>>(
        Wq, Wk, Wv, Wo, wth, wtl);

    // merged QKV projection -> split bf16 Q/K/V (Q scaled 1/8)
    gemm_mma_kernel<<<dim3(3 * DD / GBN, MM / GBM), 256, GEMM_SMEM_BYTES>>>(
        xh, xl, wth, wtl, bq, bk, bv,
        qh, ql, kh, kl, vh, vl, nullptr, 1);

    // attention -> split bf16 combined-head output
    attn_mma_kernel<<<dim3(SS / AQ, BB * HH), 256, ATTN_SMEM_BYTES>>>(
        qh, ql, kh, kl, vh, vl, ah, al);

    // output projection -> fp32 out
    gemm_mma_kernel<<<dim3(DD / GBN, MM / GBM), 256, GEMM_SMEM_BYTES>>>(
        ah, al, wth + 3 * WSZ, wtl + 3 * WSZ, bo, bo, bo,
        nullptr, nullptr, nullptr, nullptr, nullptr, nullptr, out, 0);
}